// round 3
// baseline (speedup 1.0000x reference)
#include <cuda_runtime.h>
#include <cstdint>
#include <math.h>

#define NB    65536
#define NHID  512
#define NLAT  128
#define NS    4
#define NROWS (NS*NB)          // 262144
#define TMAX  32

#define OFF_VECS 0
#define OFF_KLD  (33554432)            // NS*NB*NLAT
#define OFF_MU   (OFF_KLD + NB)        // 33619968
#define OFF_RED  (OFF_MU + NB*NLAT)    // 42008576

// scratch for vMF weights (no cudaMalloc allowed)
__device__ float g_w[NROWS];

struct Keys2 {
    uint32_t ka[TMAX][2];
    uint32_t kb[TMAX][2];
    uint32_t ku[TMAX][2];
};

// ---------------- Threefry-2x32 (JAX exact) ----------------
__host__ __device__ __forceinline__ void tf2x32(uint32_t k0, uint32_t k1,
                                                uint32_t x0, uint32_t x1,
                                                uint32_t& o0, uint32_t& o1) {
    uint32_t ks2 = k0 ^ k1 ^ 0x1BD11BDAu;
    x0 += k0; x1 += k1;
#define TFR(r) { x0 += x1; x1 = (x1 << (r)) | (x1 >> (32 - (r))); x1 ^= x0; }
    TFR(13) TFR(15) TFR(26) TFR(6)   x0 += k1;  x1 += ks2 + 1u;
    TFR(17) TFR(29) TFR(16) TFR(24)  x0 += ks2; x1 += k0 + 2u;
    TFR(13) TFR(15) TFR(26) TFR(6)   x0 += k0;  x1 += k1 + 3u;
    TFR(17) TFR(29) TFR(16) TFR(24)  x0 += k1;  x1 += ks2 + 4u;
    TFR(13) TFR(15) TFR(26) TFR(6)   x0 += ks2; x1 += k0 + 5u;
#undef TFR
    o0 = x0; o1 = x1;
}

// partitionable random_bits(key, 32, shape)[i] = o0 ^ o1 of TF(key, (0, i))
__device__ __forceinline__ uint32_t rbits(uint32_t k0, uint32_t k1, uint32_t idx) {
    uint32_t o0, o1;
    tf2x32(k0, k1, 0u, idx, o0, o1);
    return o0 ^ o1;
}

// uniform [0,1): bitcast(bits>>9 | 1.0f) - 1.0f  (JAX exact)
__device__ __forceinline__ float u01(uint32_t bits) {
    return __uint_as_float((bits >> 9) | 0x3f800000u) - 1.0f;
}

// XLA ErfInv32 — exact constants & op order (mul/add separate, no FMA)
__device__ __forceinline__ float erfinv_xla(float x) {
    float w = -log1pf(-__fmul_rn(x, x));
    float p;
    if (w < 5.0f) {
        w = __fsub_rn(w, 2.5f);
        p = 2.81022636e-08f;
        p = __fadd_rn(3.43273939e-07f,  __fmul_rn(p, w));
        p = __fadd_rn(-3.5233877e-06f,  __fmul_rn(p, w));
        p = __fadd_rn(-4.39150654e-06f, __fmul_rn(p, w));
        p = __fadd_rn(0.00021858087f,   __fmul_rn(p, w));
        p = __fadd_rn(-0.00125372503f,  __fmul_rn(p, w));
        p = __fadd_rn(-0.00417768164f,  __fmul_rn(p, w));
        p = __fadd_rn(0.246640727f,     __fmul_rn(p, w));
        p = __fadd_rn(1.50140941f,      __fmul_rn(p, w));
    } else {
        w = __fsub_rn(sqrtf(w), 3.0f);
        p = -0.000200214257f;
        p = __fadd_rn(0.000100950558f,  __fmul_rn(p, w));
        p = __fadd_rn(0.00134934322f,   __fmul_rn(p, w));
        p = __fadd_rn(-0.00367342844f,  __fmul_rn(p, w));
        p = __fadd_rn(0.00573950773f,   __fmul_rn(p, w));
        p = __fadd_rn(-0.0076224613f,   __fmul_rn(p, w));
        p = __fadd_rn(0.00943887047f,   __fmul_rn(p, w));
        p = __fadd_rn(1.00167406f,      __fmul_rn(p, w));
        p = __fadd_rn(2.83297682f,      __fmul_rn(p, w));
    }
    return __fmul_rn(p, x);
}

// jax.random.normal: u = f*2.0 + nextafter(-1,0); clamp; sqrt(2)*erfinv(u)
__device__ __forceinline__ float jax_normal(uint32_t bits) {
    const float lo = -0.99999994f;            // nextafterf(-1,0)
    float f = u01(bits);
    float u = __fadd_rn(__fmul_rn(f, 2.0f), lo);   // (hi-lo) rounds to exactly 2.0f
    u = fmaxf(lo, u);
    return __fmul_rn(1.41421356237f, erfinv_xla(u));  // f32(sqrt(2))
}

// jax _gamma_one(key, alpha=63.5, log_space=True) — Marsaglia-Tsang, exact chain
__device__ __forceinline__ float log_gamma_one(uint32_t gk0, uint32_t gk1) {
    const float one_third = 0.33333334f;               // f32(1/3)
    float dg = __fsub_rn(63.5f, one_third);
    float cg = __fdiv_rn(one_third, sqrtf(dg));

    uint32_t key0, key1;
    tf2x32(gk0, gk1, 0u, 0u, key0, key1);  // boost split: chain key = split(gkey,2)[0]

    while (true) {
        uint32_t nk0, nk1, xk0, xk1, Uk0, Uk1;
        tf2x32(key0, key1, 0u, 0u, nk0, nk1);
        tf2x32(key0, key1, 0u, 1u, xk0, xk1);
        tf2x32(key0, key1, 0u, 2u, Uk0, Uk1);
        key0 = nk0; key1 = nk1;

        // inner loop: while v <= 0 (normal draw)
        float x, v;
        uint32_t cx0 = xk0, cx1 = xk1;
        while (true) {
            uint32_t s0, s1;
            tf2x32(cx0, cx1, 0u, 1u, s0, s1);   // subkey = split(x_key,2)[1]
            x = jax_normal(rbits(s0, s1, 0u));
            v = __fadd_rn(1.0f, __fmul_rn(x, cg));
            if (v > 0.0f) break;
            uint32_t n0, n1;
            tf2x32(cx0, cx1, 0u, 0u, n0, n1);   // x_key = split(x_key,2)[0]
            cx0 = n0; cx1 = n1;
        }

        float X = __fmul_rn(x, x);
        float V = __fmul_rn(__fmul_rn(v, v), v);
        float U = u01(rbits(Uk0, Uk1, 0u));

        // continue iff (U >= 1 - 0.0331*X*X) && (log U >= 0.5X + d*((1-V)+logV))
        float sq = __fsub_rn(1.0f, __fmul_rn(0.0331f, __fmul_rn(X, X)));
        bool cont;
        if (U < sq) {
            cont = false;
        } else {
            float th = __fadd_rn(__fmul_rn(X, 0.5f),
                                 __fmul_rn(dg, __fadd_rn(__fsub_rn(1.0f, V), logf(V))));
            cont = (logf(U) >= th);
        }
        if (!cont) return __fadd_rn(logf(V), logf(dg));
    }
}

// ---------------- Kernel 1: SGEMM + norm/mu/red/kld epilogue ----------------
__global__ __launch_bounds__(256) void gemm_mu_kernel(
    const float* __restrict__ A,     // lat_code (65536, 512)
    const float* __restrict__ W,     // W_mu (128, 512)
    const float* __restrict__ bias,  // (128,)
    float* __restrict__ out, float kld)
{
    __shared__ float sA[8][132];
    __shared__ float sB[8][132];
    __shared__ float sred[128 * 16];
    __shared__ float snorm[128];

    int t = threadIdx.x;
    int m0 = blockIdx.x * 128;
    int lr = t >> 1;              // 0..127
    int lk = (t & 1) * 4;         // 0 or 4
    const float* Ag = A + (size_t)(m0 + lr) * NHID + lk;
    const float* Wg = W + (size_t)lr * NHID + lk;
    int tx = t & 15, ty = t >> 4;

    float acc[8][8];
#pragma unroll
    for (int i = 0; i < 8; i++)
#pragma unroll
        for (int j = 0; j < 8; j++) acc[i][j] = 0.0f;

    for (int kt = 0; kt < NHID; kt += 8) {
        float4 av = *(const float4*)(Ag + kt);
        float4 wv = *(const float4*)(Wg + kt);
        __syncthreads();
        sA[lk + 0][lr] = av.x; sA[lk + 1][lr] = av.y; sA[lk + 2][lr] = av.z; sA[lk + 3][lr] = av.w;
        sB[lk + 0][lr] = wv.x; sB[lk + 1][lr] = wv.y; sB[lk + 2][lr] = wv.z; sB[lk + 3][lr] = wv.w;
        __syncthreads();
#pragma unroll
        for (int k = 0; k < 8; k++) {
            float4 a0 = *(const float4*)&sA[k][ty * 8];
            float4 a1 = *(const float4*)&sA[k][ty * 8 + 4];
            float4 b0 = *(const float4*)&sB[k][tx * 8];
            float4 b1 = *(const float4*)&sB[k][tx * 8 + 4];
            float ar[8] = {a0.x, a0.y, a0.z, a0.w, a1.x, a1.y, a1.z, a1.w};
            float br[8] = {b0.x, b0.y, b0.z, b0.w, b1.x, b1.y, b1.z, b1.w};
#pragma unroll
            for (int i = 0; i < 8; i++)
#pragma unroll
                for (int j = 0; j < 8; j++) acc[i][j] += ar[i] * br[j];
        }
    }

    // bias add (b_mu)
    float4 bb0 = *(const float4*)&bias[tx * 8];
    float4 bb1 = *(const float4*)&bias[tx * 8 + 4];
    float bb[8] = {bb0.x, bb0.y, bb0.z, bb0.w, bb1.x, bb1.y, bb1.z, bb1.w};
#pragma unroll
    for (int i = 0; i < 8; i++)
#pragma unroll
        for (int j = 0; j < 8; j++) acc[i][j] += bb[j];

    // partial sum of squares per row
#pragma unroll
    for (int i = 0; i < 8; i++) {
        float s = 0.0f;
#pragma unroll
        for (int j = 0; j < 8; j++) s += acc[i][j] * acc[i][j];
        sred[(ty * 8 + i) * 16 + tx] = s;
    }
    __syncthreads();
    if (t < 128) {
        float s = 0.0f;
#pragma unroll
        for (int q = 0; q < 16; q++) s += sred[t * 16 + q];
        float nrm = sqrtf(s);
        snorm[t] = nrm;
        int grow = m0 + t;
        float om = 1.0f - nrm;
        out[OFF_RED + grow] = om * om;
        out[OFF_KLD + grow] = kld;
    }
    __syncthreads();

    float* muout = out + OFF_MU;
#pragma unroll
    for (int i = 0; i < 8; i++) {
        int r = ty * 8 + i;
        float nrm = snorm[r];
        size_t base = (size_t)(m0 + r) * NLAT + tx * 8;
        float4 v0, v1;
        v0.x = acc[i][0] / nrm; v0.y = acc[i][1] / nrm;
        v0.z = acc[i][2] / nrm; v0.w = acc[i][3] / nrm;
        v1.x = acc[i][4] / nrm; v1.y = acc[i][5] / nrm;
        v1.z = acc[i][6] / nrm; v1.w = acc[i][7] / nrm;
        *(float4*)&muout[base] = v0;
        *(float4*)&muout[base + 4] = v1;
    }
}

// ---------------- Kernel 2: vMF weight rejection sampler ----------------
__global__ __launch_bounds__(256) void wsample_kernel(Keys2 K, float A1, float A2,
                                                      float Xc, float Cc)
{
    int i = blockIdx.x * 256 + threadIdx.x;
    if (i >= NROWS) return;
    uint32_t ui = (uint32_t)i;
    float w = 0.0f;
#pragma unroll 1
    for (int t = 0; t < TMAX; t++) {
        uint32_t ga0, ga1, gb0, gb1;
        tf2x32(K.ka[t][0], K.ka[t][1], 0u, ui, ga0, ga1);   // gamma subkey a, element i
        tf2x32(K.kb[t][0], K.kb[t][1], 0u, ui, gb0, gb1);   // gamma subkey b, element i
        float lga = log_gamma_one(ga0, ga1);
        float lgb = log_gamma_one(gb0, gb1);
        float mx = fmaxf(lga, lgb);
        float gA = expf(__fsub_rn(lga, mx));
        float gB = expf(__fsub_rn(lgb, mx));
        float z = __fdiv_rn(gA, __fadd_rn(gA, gB));

        float wn = __fdiv_rn(__fsub_rn(1.0f, __fmul_rn(A1, z)),
                             __fsub_rn(1.0f, __fmul_rn(A2, z)));
        float u = u01(rbits(K.ku[t][0], K.ku[t][1], ui));
        float lhs = __fsub_rn(
            __fadd_rn(__fmul_rn(50.0f, wn),
                      __fmul_rn(127.0f, logf(__fsub_rn(1.0f, __fmul_rn(Xc, wn))))),
            Cc);
        if (lhs >= logf(u)) { w = wn; break; }
    }
    g_w[i] = w;
}

// ---------------- Kernel 3: v normals + orthogonalize + vecs ----------------
__global__ __launch_bounds__(256) void vecs_kernel(
    const float* __restrict__ mu, float* __restrict__ vecs,
    uint32_t kv0, uint32_t kv1, uint32_t kn0, uint32_t kn1)
{
    int warp = blockIdx.x * (blockDim.x >> 5) + (threadIdx.x >> 5);
    int lane = threadIdx.x & 31;
    if (warp >= NROWS) return;
    int b = warp & (NB - 1);
    const float* murow = mu + (size_t)b * NLAT;

    float m[4], v[4];
#pragma unroll
    for (int q = 0; q < 4; q++) {
        int j = lane + q * 32;
        m[q] = murow[j];
        v[q] = jax_normal(rbits(kv0, kv1, (uint32_t)warp * 128u + (uint32_t)j));
    }

    float dot = 0.0f, msq = 0.0f;
#pragma unroll
    for (int q = 0; q < 4; q++) { dot += m[q] * v[q]; msq += m[q] * m[q]; }
#pragma unroll
    for (int o = 16; o; o >>= 1) {
        dot += __shfl_xor_sync(0xffffffffu, dot, o);
        msq += __shfl_xor_sync(0xffffffffu, msq, o);
    }
    float mu_n = sqrtf(msq);
    float tproj = dot / mu_n;

    float og[4];
    float osq = 0.0f;
#pragma unroll
    for (int q = 0; q < 4; q++) { og[q] = v[q] - m[q] * tproj; osq += og[q] * og[q]; }
#pragma unroll
    for (int o = 16; o; o >>= 1) osq += __shfl_xor_sync(0xffffffffu, osq, o);
    float onorm = sqrtf(osq);

    float w = 0.0f, nn = 0.0f;
    if (lane == 0) {
        w = g_w[warp];
        nn = 1.0f + u01(rbits(kn0, kn1, (uint32_t)warp));   // 1 + uniform*NORM_EPS
    }
    w = __shfl_sync(0xffffffffu, w, 0);
    nn = __shfl_sync(0xffffffffu, nn, 0);
    float s = sqrtf(1.0f - w * w);

    float* outrow = vecs + (size_t)warp * NLAT;
#pragma unroll
    for (int q = 0; q < 4; q++) {
        int j = lane + q * 32;
        float vo = og[q] / onorm;
        outrow[j] = (vo * s + m[q] * w) * nn;
    }
}

// ---------------- Host: constants, keys, launch ----------------
static double host_log_iv(double nu, double k) {
    const int M = 300;
    double logt[M];
    double mx = -1e300;
    for (int m = 0; m < M; m++) {
        double t = (2.0 * m + nu) * log(k / 2.0) - lgamma(m + 1.0) - lgamma(m + nu + 1.0);
        logt[m] = t;
        if (t > mx) mx = t;
    }
    double s = 0.0;
    for (int m = 0; m < M; m++) s += exp(logt[m] - mx);
    return mx + log(s);
}

extern "C" void kernel_launch(void* const* d_in, const int* in_sizes, int n_in,
                              void* d_out, int out_size)
{
    const float* lat = (const float*)d_in[0];
    const float* Wm  = (const float*)d_in[1];
    const float* bm  = (const float*)d_in[2];
    float* out = (float*)d_out;

    // vMF sampler constants (double, as in reference host code)
    const double dd = 127.0, kap = 50.0;
    double b = dd / (sqrt(4.0 * kap * kap + dd * dd) + 2.0 * kap);
    double x = (1.0 - b) / (1.0 + b);
    double c = kap * x + dd * log(1.0 - x * x);
    float A1 = (float)(1.0 + b), A2 = (float)(1.0 - b);
    float Xc = (float)x, Cc = (float)c;

    // KLD constant (d = LAT_DIM = 128 here)
    const double D = 128.0;
    double liv0 = host_log_iv(D / 2.0, kap);
    double liv1 = host_log_iv(D / 2.0 + 1.0, kap);
    double ratio = exp(liv1 - liv0);
    double a_ = D / (2.0 * kap);
    double vmf = kap * (ratio + a_ - a_) + D * log(kap) / 2.0 - liv0
               - lgamma(D / 2.0 + 1.0) - D * log(2.0) / 2.0;
    double kld_d = vmf + log(2.0 / 1.0);
    float kld = (float)kld_d;

    // Key derivation (host threefry): key(1) = (0,1); kw,kv,kn = split(key,3)
    uint32_t kw0, kw1, kv0, kv1, kn0, kn1;
    tf2x32(0u, 1u, 0u, 0u, kw0, kw1);
    tf2x32(0u, 1u, 0u, 1u, kv0, kv1);
    tf2x32(0u, 1u, 0u, 2u, kn0, kn1);

    // Per-iteration sampler keys: (key, kz, ku) = split(key,3); (ka,kb) = split(kz,2)
    Keys2 K;
    uint32_t c0 = kw0, c1 = kw1;
    for (int t = 0; t < TMAX; t++) {
        uint32_t nk0, nk1, kz0, kz1, ku0, ku1;
        tf2x32(c0, c1, 0u, 0u, nk0, nk1);
        tf2x32(c0, c1, 0u, 1u, kz0, kz1);
        tf2x32(c0, c1, 0u, 2u, ku0, ku1);
        tf2x32(kz0, kz1, 0u, 0u, K.ka[t][0], K.ka[t][1]);
        tf2x32(kz0, kz1, 0u, 1u, K.kb[t][0], K.kb[t][1]);
        K.ku[t][0] = ku0; K.ku[t][1] = ku1;
        c0 = nk0; c1 = nk1;
    }

    gemm_mu_kernel<<<NB / 128, 256>>>(lat, Wm, bm, out, kld);
    wsample_kernel<<<NROWS / 256, 256>>>(K, A1, A2, Xc, Cc);
    vecs_kernel<<<NROWS / 8, 256>>>(out + OFF_MU, out + OFF_VECS, kv0, kv1, kn0, kn1);
}

// round 5
// speedup vs baseline: 1.1225x; 1.1225x over previous
#include <cuda_runtime.h>
#include <cuda_bf16.h>
#include <cstdint>
#include <math.h>

#define NB    65536
#define NHID  512
#define NLAT  128
#define NS    4
#define NROWS (NS*NB)          // 262144
#define TMAX  32

#define OFF_VECS 0
#define OFF_KLD  (33554432)            // NS*NB*NLAT
#define OFF_MU   (OFF_KLD + NB)        // 33619968
#define OFF_RED  (OFF_MU + NB*NLAT)    // 42008576

// scratch for vMF weights (no cudaMalloc allowed)
__device__ float g_w[NROWS];

struct Keys2 {
    uint32_t ka[TMAX][2];
    uint32_t kb[TMAX][2];
    uint32_t ku[TMAX][2];
};

// ---------------- Threefry-2x32 (JAX exact) ----------------
__host__ __device__ __forceinline__ void tf2x32(uint32_t k0, uint32_t k1,
                                                uint32_t x0, uint32_t x1,
                                                uint32_t& o0, uint32_t& o1) {
    uint32_t ks2 = k0 ^ k1 ^ 0x1BD11BDAu;
    x0 += k0; x1 += k1;
#define TFR(r) { x0 += x1; x1 = (x1 << (r)) | (x1 >> (32 - (r))); x1 ^= x0; }
    TFR(13) TFR(15) TFR(26) TFR(6)   x0 += k1;  x1 += ks2 + 1u;
    TFR(17) TFR(29) TFR(16) TFR(24)  x0 += ks2; x1 += k0 + 2u;
    TFR(13) TFR(15) TFR(26) TFR(6)   x0 += k0;  x1 += k1 + 3u;
    TFR(17) TFR(29) TFR(16) TFR(24)  x0 += k1;  x1 += ks2 + 4u;
    TFR(13) TFR(15) TFR(26) TFR(6)   x0 += ks2; x1 += k0 + 5u;
#undef TFR
    o0 = x0; o1 = x1;
}

__device__ __forceinline__ uint32_t rbits(uint32_t k0, uint32_t k1, uint32_t idx) {
    uint32_t o0, o1;
    tf2x32(k0, k1, 0u, idx, o0, o1);
    return o0 ^ o1;
}

__device__ __forceinline__ float u01(uint32_t bits) {
    return __uint_as_float((bits >> 9) | 0x3f800000u) - 1.0f;
}

// XLA ErfInv32 — exact constants & op order
__device__ __forceinline__ float erfinv_xla(float x) {
    float w = -log1pf(-__fmul_rn(x, x));
    float p;
    if (w < 5.0f) {
        w = __fsub_rn(w, 2.5f);
        p = 2.81022636e-08f;
        p = __fadd_rn(3.43273939e-07f,  __fmul_rn(p, w));
        p = __fadd_rn(-3.5233877e-06f,  __fmul_rn(p, w));
        p = __fadd_rn(-4.39150654e-06f, __fmul_rn(p, w));
        p = __fadd_rn(0.00021858087f,   __fmul_rn(p, w));
        p = __fadd_rn(-0.00125372503f,  __fmul_rn(p, w));
        p = __fadd_rn(-0.00417768164f,  __fmul_rn(p, w));
        p = __fadd_rn(0.246640727f,     __fmul_rn(p, w));
        p = __fadd_rn(1.50140941f,      __fmul_rn(p, w));
    } else {
        w = __fsub_rn(sqrtf(w), 3.0f);
        p = -0.000200214257f;
        p = __fadd_rn(0.000100950558f,  __fmul_rn(p, w));
        p = __fadd_rn(0.00134934322f,   __fmul_rn(p, w));
        p = __fadd_rn(-0.00367342844f,  __fmul_rn(p, w));
        p = __fadd_rn(0.00573950773f,   __fmul_rn(p, w));
        p = __fadd_rn(-0.0076224613f,   __fmul_rn(p, w));
        p = __fadd_rn(0.00943887047f,   __fmul_rn(p, w));
        p = __fadd_rn(1.00167406f,      __fmul_rn(p, w));
        p = __fadd_rn(2.83297682f,      __fmul_rn(p, w));
    }
    return __fmul_rn(p, x);
}

__device__ __forceinline__ float jax_normal(uint32_t bits) {
    const float lo = -0.99999994f;
    float f = u01(bits);
    float u = __fadd_rn(__fmul_rn(f, 2.0f), lo);
    u = fmaxf(lo, u);
    return __fmul_rn(1.41421356237f, erfinv_xla(u));
}

// jax _gamma_one(key, alpha=63.5, log_space=True) — exact chain
__device__ __forceinline__ float log_gamma_one(uint32_t gk0, uint32_t gk1) {
    const float one_third = 0.33333334f;
    float dg = __fsub_rn(63.5f, one_third);
    float cg = __fdiv_rn(one_third, sqrtf(dg));

    uint32_t key0, key1;
    tf2x32(gk0, gk1, 0u, 0u, key0, key1);

    while (true) {
        uint32_t nk0, nk1, xk0, xk1, Uk0, Uk1;
        tf2x32(key0, key1, 0u, 0u, nk0, nk1);
        tf2x32(key0, key1, 0u, 1u, xk0, xk1);
        tf2x32(key0, key1, 0u, 2u, Uk0, Uk1);
        key0 = nk0; key1 = nk1;

        float x, v;
        uint32_t cx0 = xk0, cx1 = xk1;
        while (true) {
            uint32_t s0, s1;
            tf2x32(cx0, cx1, 0u, 1u, s0, s1);
            x = jax_normal(rbits(s0, s1, 0u));
            v = __fadd_rn(1.0f, __fmul_rn(x, cg));
            if (v > 0.0f) break;
            uint32_t n0, n1;
            tf2x32(cx0, cx1, 0u, 0u, n0, n1);
            cx0 = n0; cx1 = n1;
        }

        float X = __fmul_rn(x, x);
        float V = __fmul_rn(__fmul_rn(v, v), v);
        float U = u01(rbits(Uk0, Uk1, 0u));

        float sq = __fsub_rn(1.0f, __fmul_rn(0.0331f, __fmul_rn(X, X)));
        bool cont;
        if (U < sq) {
            cont = false;
        } else {
            float th = __fadd_rn(__fmul_rn(X, 0.5f),
                                 __fmul_rn(dg, __fadd_rn(__fsub_rn(1.0f, V), logf(V))));
            cont = (logf(U) >= th);
        }
        if (!cont) return __fadd_rn(logf(V), logf(dg));
    }
}

// ================= mma.sync helpers (arch-agnostic PTX, works on sm_100) =====
__device__ __forceinline__ uint32_t smem_u32(const void* p) {
    uint32_t a;
    asm("{ .reg .u64 t; cvta.to.shared.u64 t, %1; cvt.u32.u64 %0, t; }"
        : "=r"(a) : "l"(p));
    return a;
}
#define SWZ128(o) ((o) ^ (((o) >> 3) & 0x70))

#define LDM4(r, addr)                                                              \
    asm volatile("ldmatrix.sync.aligned.m8n8.x4.shared.b16 {%0,%1,%2,%3}, [%4];"   \
        : "=r"((r)[0]), "=r"((r)[1]), "=r"((r)[2]), "=r"((r)[3]) : "r"(addr))

#define MMA16816(c, a, b0, b1)                                                     \
    asm volatile("mma.sync.aligned.m16n8k16.row.col.f32.bf16.bf16.f32 "            \
        "{%0,%1,%2,%3}, {%4,%5,%6,%7}, {%8,%9}, {%0,%1,%2,%3};"                    \
        : "+f"((c)[0]), "+f"((c)[1]), "+f"((c)[2]), "+f"((c)[3])                   \
        : "r"((a)[0]), "r"((a)[1]), "r"((a)[2]), "r"((a)[3]), "r"(b0), "r"(b1))

__device__ __forceinline__ uint32_t pack_bf2(float a, float b) {
    __nv_bfloat162 t = __floats2bfloat162_rn(a, b);
    return *reinterpret_cast<uint32_t*>(&t);
}
__device__ __forceinline__ float bf_residual(float a) {
    __nv_bfloat16 h = __float2bfloat16_rn(a);
    return __fsub_rn(a, __bfloat162float(h));
}

// smem layout (byte offsets from 1024-aligned base)
#define SM_BIAS   0        // 128 f32
#define SM_NORM   512      // 128 f32
#define SM_NPART  1024     // 128*2 f32
#define SM_OPND   2048     // 4 x 16KB bf16 operand buffers; reused as staging
#define SM_AHI    (SM_OPND + 0)
#define SM_ALO    (SM_OPND + 16384)
#define SM_BHI    (SM_OPND + 32768)
#define SM_BLO    (SM_OPND + 49152)
#define STG_STRIDE 132     // floats per staged row (pad 4)
#define SM_DYN    (2048 + 128*STG_STRIDE*4 + 1024)   // 70656 (covers operands too)

// ---------------- Kernel 1: mma.sync split-bf16 SGEMM + epilogue ----------------
__global__ __launch_bounds__(256) void gemm_mu_kernel(
    const float* __restrict__ A,     // lat_code (65536, 512)
    const float* __restrict__ W,     // W_mu (128, 512)
    const float* __restrict__ bias,  // (128,)
    float* __restrict__ out, float kld)
{
    extern __shared__ char dsm[];
    char* p = (char*)(((uintptr_t)dsm + 1023) & ~(uintptr_t)1023);
    uint32_t sb = smem_u32(p);

    int t = threadIdx.x;
    int wid = t >> 5;
    int lane = t & 31;
    int m0 = blockIdx.x * 128;

    int warp_m = wid & 3;            // 0..3  -> rows 32*warp_m
    int warp_n = wid >> 2;           // 0..1  -> cols 64*warp_n
    int m0w = warp_m * 32;
    int n0w = warp_n * 64;

    if (t < 128) *(float*)(p + SM_BIAS + t * 4) = bias[t];

    float c[2][8][4];
#pragma unroll
    for (int mt = 0; mt < 2; mt++)
#pragma unroll
        for (int nt = 0; nt < 8; nt++)
#pragma unroll
            for (int q = 0; q < 4; q++) c[mt][nt][q] = 0.0f;

    // ldmatrix lane-address components
    int a_row = (lane & 7) + ((lane >> 3) & 1) * 8;   // + m0w + mt*16
    int a_kb  = (lane >> 4) * 16;                      // + ks*32
    int b_row = (lane & 7) + (lane >> 4) * 8;          // + n0w + half*32 + g*16
    int b_kb  = ((lane >> 3) & 1) * 16;                // + ks*32

    for (int kb = 0; kb < 8; kb++) {
        // prefetch chunk (A: 8 float4, B: 8 float4 per thread)
        float4 ra[8], rb[8];
#pragma unroll
        for (int q = 0; q < 8; q++) {
            int fidx = t * 8 + q;
            int row = fidx >> 4;
            int kq = (fidx & 15) << 2;
            ra[q] = *(const float4*)(A + (size_t)(m0 + row) * NHID + kb * 64 + kq);
            rb[q] = *(const float4*)(W + (size_t)row * NHID + kb * 64 + kq);
        }
        __syncthreads();   // previous chunk's ldmatrix reads done
#pragma unroll
        for (int q = 0; q < 8; q++) {
            int fidx = t * 8 + q;
            int row = fidx >> 4;
            int kq = (fidx & 15) << 2;
            uint32_t off = SWZ128((uint32_t)(row * 128 + kq * 2));
            float4 a = ra[q], b = rb[q];
            *(uint2*)(p + SM_AHI + off) = make_uint2(pack_bf2(a.x, a.y), pack_bf2(a.z, a.w));
            *(uint2*)(p + SM_ALO + off) = make_uint2(pack_bf2(bf_residual(a.x), bf_residual(a.y)),
                                                     pack_bf2(bf_residual(a.z), bf_residual(a.w)));
            *(uint2*)(p + SM_BHI + off) = make_uint2(pack_bf2(b.x, b.y), pack_bf2(b.z, b.w));
            *(uint2*)(p + SM_BLO + off) = make_uint2(pack_bf2(bf_residual(b.x), bf_residual(b.y)),
                                                     pack_bf2(bf_residual(b.z), bf_residual(b.w)));
        }
        __syncthreads();

#pragma unroll
        for (int ks = 0; ks < 4; ks++) {
            int kb2 = ks * 32;
            uint32_t ah[2][4], al[2][4];
#pragma unroll
            for (int mt = 0; mt < 2; mt++) {
                uint32_t off = SWZ128((uint32_t)(((m0w + mt * 16 + a_row) << 7) + kb2 + a_kb));
                LDM4(ah[mt], sb + SM_AHI + off);
                LDM4(al[mt], sb + SM_ALO + off);
            }
#pragma unroll
            for (int half = 0; half < 2; half++) {
                uint32_t bh[2][4], bl[2][4];
#pragma unroll
                for (int g = 0; g < 2; g++) {
                    uint32_t off = SWZ128((uint32_t)(((n0w + half * 32 + g * 16 + b_row) << 7) + kb2 + b_kb));
                    LDM4(bh[g], sb + SM_BHI + off);
                    LDM4(bl[g], sb + SM_BLO + off);
                }
#pragma unroll
                for (int mt = 0; mt < 2; mt++)
#pragma unroll
                    for (int n4 = 0; n4 < 4; n4++) {
                        int g = n4 >> 1, wch = (n4 & 1) * 2;
                        float* cc = c[mt][half * 4 + n4];
                        MMA16816(cc, ah[mt], bh[g][wch], bh[g][wch + 1]);
                        MMA16816(cc, ah[mt], bl[g][wch], bl[g][wch + 1]);
                        MMA16816(cc, al[mt], bh[g][wch], bh[g][wch + 1]);
                    }
            }
        }
    }
    __syncthreads();   // all warps done reading operand smem -> reuse as staging

    // bias add + row sum of squares
    float* bias_s = (float*)(p + SM_BIAS);
    float* norm_s = (float*)(p + SM_NORM);
    float* npart  = (float*)(p + SM_NPART);
    float* stg    = (float*)(p + SM_OPND);

    float rs[4] = {0.0f, 0.0f, 0.0f, 0.0f};
#pragma unroll
    for (int nt = 0; nt < 8; nt++) {
        int col = n0w + nt * 8 + 2 * (lane & 3);
        float b0 = bias_s[col], b1 = bias_s[col + 1];
#pragma unroll
        for (int mt = 0; mt < 2; mt++) {
            c[mt][nt][0] += b0; c[mt][nt][1] += b1;
            c[mt][nt][2] += b0; c[mt][nt][3] += b1;
            rs[mt * 2 + 0] += c[mt][nt][0] * c[mt][nt][0] + c[mt][nt][1] * c[mt][nt][1];
            rs[mt * 2 + 1] += c[mt][nt][2] * c[mt][nt][2] + c[mt][nt][3] * c[mt][nt][3];
            int row = m0w + mt * 16 + (lane >> 2);
            *(float2*)(stg + row * STG_STRIDE + col) = make_float2(c[mt][nt][0], c[mt][nt][1]);
            *(float2*)(stg + (row + 8) * STG_STRIDE + col) = make_float2(c[mt][nt][2], c[mt][nt][3]);
        }
    }
#pragma unroll
    for (int i = 0; i < 4; i++) {
        rs[i] += __shfl_xor_sync(0xffffffffu, rs[i], 1);
        rs[i] += __shfl_xor_sync(0xffffffffu, rs[i], 2);
    }
    if ((lane & 3) == 0) {
        int rbase = m0w + (lane >> 2);
#pragma unroll
        for (int i = 0; i < 4; i++)
            npart[(rbase + i * 8) * 2 + warp_n] = rs[i];
    }
    __syncthreads();

    if (t < 128) {
        float nrm = sqrtf(npart[t * 2] + npart[t * 2 + 1]);
        norm_s[t] = nrm;
        int grow = m0 + t;
        float om = 1.0f - nrm;
        out[OFF_RED + grow] = om * om;
        out[OFF_KLD + grow] = kld;
    }
    __syncthreads();

    // coalesced mu writeout
    float4* muv = (float4*)(out + OFF_MU + (size_t)m0 * NLAT);
#pragma unroll
    for (int j = 0; j < 16; j++) {
        int idx = t * 16 + j;          // float4 units, 0..4095
        int r = idx >> 5;
        int c4 = idx & 31;
        float4 v = *(float4*)(stg + r * STG_STRIDE + c4 * 4);
        float nrm = norm_s[r];
        v.x /= nrm; v.y /= nrm; v.z /= nrm; v.w /= nrm;
        muv[r * 32 + c4] = v;
    }
}

// ---------------- Kernel 2: vMF weight rejection sampler ----------------
__global__ __launch_bounds__(256) void wsample_kernel(Keys2 K, float A1, float A2,
                                                      float Xc, float Cc)
{
    int i = blockIdx.x * 256 + threadIdx.x;
    if (i >= NROWS) return;
    uint32_t ui = (uint32_t)i;
    float w = 0.0f;
#pragma unroll 1
    for (int t = 0; t < TMAX; t++) {
        uint32_t ga0, ga1, gb0, gb1;
        tf2x32(K.ka[t][0], K.ka[t][1], 0u, ui, ga0, ga1);
        tf2x32(K.kb[t][0], K.kb[t][1], 0u, ui, gb0, gb1);
        float lga = log_gamma_one(ga0, ga1);
        float lgb = log_gamma_one(gb0, gb1);
        float mx = fmaxf(lga, lgb);
        float gA = expf(__fsub_rn(lga, mx));
        float gB = expf(__fsub_rn(lgb, mx));
        float z = __fdiv_rn(gA, __fadd_rn(gA, gB));

        float wn = __fdiv_rn(__fsub_rn(1.0f, __fmul_rn(A1, z)),
                             __fsub_rn(1.0f, __fmul_rn(A2, z)));
        float u = u01(rbits(K.ku[t][0], K.ku[t][1], ui));
        float lhs = __fsub_rn(
            __fadd_rn(__fmul_rn(50.0f, wn),
                      __fmul_rn(127.0f, logf(__fsub_rn(1.0f, __fmul_rn(Xc, wn))))),
            Cc);
        if (lhs >= logf(u)) { w = wn; break; }
    }
    g_w[i] = w;
}

// ---------------- Kernel 3: v normals + orthogonalize + vecs ----------------
__global__ __launch_bounds__(256) void vecs_kernel(
    const float* __restrict__ mu, float* __restrict__ vecs,
    uint32_t kv0, uint32_t kv1, uint32_t kn0, uint32_t kn1)
{
    int warp = blockIdx.x * (blockDim.x >> 5) + (threadIdx.x >> 5);
    int lane = threadIdx.x & 31;
    if (warp >= NROWS) return;
    int b = warp & (NB - 1);
    const float* murow = mu + (size_t)b * NLAT;

    float m[4], v[4];
#pragma unroll
    for (int q = 0; q < 4; q++) {
        int j = lane + q * 32;
        m[q] = murow[j];
        v[q] = jax_normal(rbits(kv0, kv1, (uint32_t)warp * 128u + (uint32_t)j));
    }

    float dot = 0.0f, msq = 0.0f;
#pragma unroll
    for (int q = 0; q < 4; q++) { dot += m[q] * v[q]; msq += m[q] * m[q]; }
#pragma unroll
    for (int o = 16; o; o >>= 1) {
        dot += __shfl_xor_sync(0xffffffffu, dot, o);
        msq += __shfl_xor_sync(0xffffffffu, msq, o);
    }
    float mu_n = sqrtf(msq);
    float tproj = dot / mu_n;

    float og[4];
    float osq = 0.0f;
#pragma unroll
    for (int q = 0; q < 4; q++) { og[q] = v[q] - m[q] * tproj; osq += og[q] * og[q]; }
#pragma unroll
    for (int o = 16; o; o >>= 1) osq += __shfl_xor_sync(0xffffffffu, osq, o);
    float onorm = sqrtf(osq);

    float w = 0.0f, nn = 0.0f;
    if (lane == 0) {
        w = g_w[warp];
        nn = 1.0f + u01(rbits(kn0, kn1, (uint32_t)warp));
    }
    w = __shfl_sync(0xffffffffu, w, 0);
    nn = __shfl_sync(0xffffffffu, nn, 0);
    float s = sqrtf(1.0f - w * w);

    float* outrow = vecs + (size_t)warp * NLAT;
#pragma unroll
    for (int q = 0; q < 4; q++) {
        int j = lane + q * 32;
        float vo = og[q] / onorm;
        outrow[j] = (vo * s + m[q] * w) * nn;
    }
}

// ---------------- Host ----------------
static double host_log_iv(double nu, double k) {
    const int M = 300;
    double logt[M];
    double mx = -1e300;
    for (int m = 0; m < M; m++) {
        double tv = (2.0 * m + nu) * log(k / 2.0) - lgamma(m + 1.0) - lgamma(m + nu + 1.0);
        logt[m] = tv;
        if (tv > mx) mx = tv;
    }
    double s = 0.0;
    for (int m = 0; m < M; m++) s += exp(logt[m] - mx);
    return mx + log(s);
}

extern "C" void kernel_launch(void* const* d_in, const int* in_sizes, int n_in,
                              void* d_out, int out_size)
{
    const float* lat = (const float*)d_in[0];
    const float* Wm  = (const float*)d_in[1];
    const float* bm  = (const float*)d_in[2];
    float* out = (float*)d_out;

    const double dd = 127.0, kap = 50.0;
    double b = dd / (sqrt(4.0 * kap * kap + dd * dd) + 2.0 * kap);
    double x = (1.0 - b) / (1.0 + b);
    double c = kap * x + dd * log(1.0 - x * x);
    float A1 = (float)(1.0 + b), A2 = (float)(1.0 - b);
    float Xc = (float)x, Cc = (float)c;

    const double D = 128.0;
    double liv0 = host_log_iv(D / 2.0, kap);
    double liv1 = host_log_iv(D / 2.0 + 1.0, kap);
    double ratio = exp(liv1 - liv0);
    double a_ = D / (2.0 * kap);
    double vmf = kap * (ratio + a_ - a_) + D * log(kap) / 2.0 - liv0
               - lgamma(D / 2.0 + 1.0) - D * log(2.0) / 2.0;
    float kld = (float)(vmf + log(2.0 / 1.0));

    uint32_t kw0, kw1, kv0, kv1, kn0, kn1;
    tf2x32(0u, 1u, 0u, 0u, kw0, kw1);
    tf2x32(0u, 1u, 0u, 1u, kv0, kv1);
    tf2x32(0u, 1u, 0u, 2u, kn0, kn1);

    Keys2 K;
    uint32_t c0 = kw0, c1 = kw1;
    for (int t = 0; t < TMAX; t++) {
        uint32_t nk0, nk1, kz0, kz1, ku0, ku1;
        tf2x32(c0, c1, 0u, 0u, nk0, nk1);
        tf2x32(c0, c1, 0u, 1u, kz0, kz1);
        tf2x32(c0, c1, 0u, 2u, ku0, ku1);
        tf2x32(kz0, kz1, 0u, 0u, K.ka[t][0], K.ka[t][1]);
        tf2x32(kz0, kz1, 0u, 1u, K.kb[t][0], K.kb[t][1]);
        K.ku[t][0] = ku0; K.ku[t][1] = ku1;
        c0 = nk0; c1 = nk1;
    }

    cudaFuncSetAttribute(gemm_mu_kernel,
                         cudaFuncAttributeMaxDynamicSharedMemorySize, SM_DYN);

    wsample_kernel<<<NROWS / 256, 256>>>(K, A1, A2, Xc, Cc);
    gemm_mu_kernel<<<NB / 128, 256, SM_DYN>>>(lat, Wm, bm, out, kld);
    vecs_kernel<<<NROWS / 8, 256>>>(out + OFF_MU, out + OFF_VECS, kv0, kv1, kn0, kn1);
}

// round 6
// speedup vs baseline: 1.2032x; 1.0719x over previous
#include <cuda_runtime.h>
#include <cuda_bf16.h>
#include <cstdint>
#include <math.h>

#define NB    65536
#define NHID  512
#define NLAT  128
#define NS    4
#define NROWS (NS*NB)          // 262144
#define NVTOT (NROWS*NLAT)     // 33554432
#define TMAX  32

#define OFF_VECS 0
#define OFF_KLD  (33554432)            // NS*NB*NLAT
#define OFF_MU   (OFF_KLD + NB)        // 33619968
#define OFF_RED  (OFF_MU + NB*NLAT)    // 42008576

// scratch (no cudaMalloc allowed): vMF weights + raw normal draws
__device__ float g_w[NROWS];
__device__ float g_v[NVTOT];

struct Keys2 {
    uint32_t ka[TMAX][2];
    uint32_t kb[TMAX][2];
    uint32_t ku[TMAX][2];
};

// ---------------- Threefry-2x32 (JAX exact) ----------------
__host__ __device__ __forceinline__ void tf2x32(uint32_t k0, uint32_t k1,
                                                uint32_t x0, uint32_t x1,
                                                uint32_t& o0, uint32_t& o1) {
    uint32_t ks2 = k0 ^ k1 ^ 0x1BD11BDAu;
    x0 += k0; x1 += k1;
#define TFR(r) { x0 += x1; x1 = (x1 << (r)) | (x1 >> (32 - (r))); x1 ^= x0; }
    TFR(13) TFR(15) TFR(26) TFR(6)   x0 += k1;  x1 += ks2 + 1u;
    TFR(17) TFR(29) TFR(16) TFR(24)  x0 += ks2; x1 += k0 + 2u;
    TFR(13) TFR(15) TFR(26) TFR(6)   x0 += k0;  x1 += k1 + 3u;
    TFR(17) TFR(29) TFR(16) TFR(24)  x0 += k1;  x1 += ks2 + 4u;
    TFR(13) TFR(15) TFR(26) TFR(6)   x0 += ks2; x1 += k0 + 5u;
#undef TFR
    o0 = x0; o1 = x1;
}

__device__ __forceinline__ uint32_t rbits(uint32_t k0, uint32_t k1, uint32_t idx) {
    uint32_t o0, o1;
    tf2x32(k0, k1, 0u, idx, o0, o1);
    return o0 ^ o1;
}

__device__ __forceinline__ float u01(uint32_t bits) {
    return __uint_as_float((bits >> 9) | 0x3f800000u) - 1.0f;
}

// XLA ErfInv32 — exact constants & op order
__device__ __forceinline__ float erfinv_xla(float x) {
    float w = -log1pf(-__fmul_rn(x, x));
    float p;
    if (w < 5.0f) {
        w = __fsub_rn(w, 2.5f);
        p = 2.81022636e-08f;
        p = __fadd_rn(3.43273939e-07f,  __fmul_rn(p, w));
        p = __fadd_rn(-3.5233877e-06f,  __fmul_rn(p, w));
        p = __fadd_rn(-4.39150654e-06f, __fmul_rn(p, w));
        p = __fadd_rn(0.00021858087f,   __fmul_rn(p, w));
        p = __fadd_rn(-0.00125372503f,  __fmul_rn(p, w));
        p = __fadd_rn(-0.00417768164f,  __fmul_rn(p, w));
        p = __fadd_rn(0.246640727f,     __fmul_rn(p, w));
        p = __fadd_rn(1.50140941f,      __fmul_rn(p, w));
    } else {
        w = __fsub_rn(sqrtf(w), 3.0f);
        p = -0.000200214257f;
        p = __fadd_rn(0.000100950558f,  __fmul_rn(p, w));
        p = __fadd_rn(0.00134934322f,   __fmul_rn(p, w));
        p = __fadd_rn(-0.00367342844f,  __fmul_rn(p, w));
        p = __fadd_rn(0.00573950773f,   __fmul_rn(p, w));
        p = __fadd_rn(-0.0076224613f,   __fmul_rn(p, w));
        p = __fadd_rn(0.00943887047f,   __fmul_rn(p, w));
        p = __fadd_rn(1.00167406f,      __fmul_rn(p, w));
        p = __fadd_rn(2.83297682f,      __fmul_rn(p, w));
    }
    return __fmul_rn(p, x);
}

__device__ __forceinline__ float jax_normal(uint32_t bits) {
    const float lo = -0.99999994f;
    float f = u01(bits);
    float u = __fadd_rn(__fmul_rn(f, 2.0f), lo);
    u = fmaxf(lo, u);
    return __fmul_rn(1.41421356237f, erfinv_xla(u));
}

// jax _gamma_one(key, alpha=63.5, log_space=True) — exact chain
__device__ __forceinline__ float log_gamma_one(uint32_t gk0, uint32_t gk1) {
    const float one_third = 0.33333334f;
    float dg = __fsub_rn(63.5f, one_third);
    float cg = __fdiv_rn(one_third, sqrtf(dg));

    uint32_t key0, key1;
    tf2x32(gk0, gk1, 0u, 0u, key0, key1);

    while (true) {
        uint32_t nk0, nk1, xk0, xk1, Uk0, Uk1;
        tf2x32(key0, key1, 0u, 0u, nk0, nk1);
        tf2x32(key0, key1, 0u, 1u, xk0, xk1);
        tf2x32(key0, key1, 0u, 2u, Uk0, Uk1);
        key0 = nk0; key1 = nk1;

        float x, v;
        uint32_t cx0 = xk0, cx1 = xk1;
        while (true) {
            uint32_t s0, s1;
            tf2x32(cx0, cx1, 0u, 1u, s0, s1);
            x = jax_normal(rbits(s0, s1, 0u));
            v = __fadd_rn(1.0f, __fmul_rn(x, cg));
            if (v > 0.0f) break;
            uint32_t n0, n1;
            tf2x32(cx0, cx1, 0u, 0u, n0, n1);
            cx0 = n0; cx1 = n1;
        }

        float X = __fmul_rn(x, x);
        float V = __fmul_rn(__fmul_rn(v, v), v);
        float U = u01(rbits(Uk0, Uk1, 0u));

        float sq = __fsub_rn(1.0f, __fmul_rn(0.0331f, __fmul_rn(X, X)));
        bool cont;
        if (U < sq) {
            cont = false;
        } else {
            float th = __fadd_rn(__fmul_rn(X, 0.5f),
                                 __fmul_rn(dg, __fadd_rn(__fsub_rn(1.0f, V), logf(V))));
            cont = (logf(U) >= th);
        }
        if (!cont) return __fadd_rn(logf(V), logf(dg));
    }
}

// ================= mma.sync helpers =================
__device__ __forceinline__ uint32_t smem_u32(const void* p) {
    uint32_t a;
    asm("{ .reg .u64 t; cvta.to.shared.u64 t, %1; cvt.u32.u64 %0, t; }"
        : "=r"(a) : "l"(p));
    return a;
}
#define SWZ128(o) ((o) ^ (((o) >> 3) & 0x70))

#define LDM4(r, addr)                                                              \
    asm volatile("ldmatrix.sync.aligned.m8n8.x4.shared.b16 {%0,%1,%2,%3}, [%4];"   \
        : "=r"((r)[0]), "=r"((r)[1]), "=r"((r)[2]), "=r"((r)[3]) : "r"(addr))

#define MMA16816(c, a, b0, b1)                                                     \
    asm volatile("mma.sync.aligned.m16n8k16.row.col.f32.bf16.bf16.f32 "            \
        "{%0,%1,%2,%3}, {%4,%5,%6,%7}, {%8,%9}, {%0,%1,%2,%3};"                    \
        : "+f"((c)[0]), "+f"((c)[1]), "+f"((c)[2]), "+f"((c)[3])                   \
        : "r"((a)[0]), "r"((a)[1]), "r"((a)[2]), "r"((a)[3]), "r"(b0), "r"(b1))

__device__ __forceinline__ uint32_t pack_bf2(float a, float b) {
    __nv_bfloat162 t = __floats2bfloat162_rn(a, b);
    return *reinterpret_cast<uint32_t*>(&t);
}
__device__ __forceinline__ float bf_residual(float a) {
    __nv_bfloat16 h = __float2bfloat16_rn(a);
    return __fsub_rn(a, __bfloat162float(h));
}

// smem layout (byte offsets from 1024-aligned base)
#define SM_BIAS   0
#define SM_NORM   512
#define SM_NPART  1024
#define SM_OPND   2048
#define SM_AHI    (SM_OPND + 0)
#define SM_ALO    (SM_OPND + 16384)
#define SM_BHI    (SM_OPND + 32768)
#define SM_BLO    (SM_OPND + 49152)
#define STG_STRIDE 132
#define SM_DYN    (2048 + 128*STG_STRIDE*4 + 1024)

// ---------------- Kernel 1: mma.sync split-bf16 SGEMM + epilogue ----------------
__global__ __launch_bounds__(256) void gemm_mu_kernel(
    const float* __restrict__ A,
    const float* __restrict__ W,
    const float* __restrict__ bias,
    float* __restrict__ out, float kld)
{
    extern __shared__ char dsm[];
    char* p = (char*)(((uintptr_t)dsm + 1023) & ~(uintptr_t)1023);
    uint32_t sb = smem_u32(p);

    int t = threadIdx.x;
    int wid = t >> 5;
    int lane = t & 31;
    int m0 = blockIdx.x * 128;

    int warp_m = wid & 3;
    int warp_n = wid >> 2;
    int m0w = warp_m * 32;
    int n0w = warp_n * 64;

    if (t < 128) *(float*)(p + SM_BIAS + t * 4) = bias[t];

    float c[2][8][4];
#pragma unroll
    for (int mt = 0; mt < 2; mt++)
#pragma unroll
        for (int nt = 0; nt < 8; nt++)
#pragma unroll
            for (int q = 0; q < 4; q++) c[mt][nt][q] = 0.0f;

    int a_row = (lane & 7) + ((lane >> 3) & 1) * 8;
    int a_kb  = (lane >> 4) * 16;
    int b_row = (lane & 7) + (lane >> 4) * 8;
    int b_kb  = ((lane >> 3) & 1) * 16;

    for (int kb = 0; kb < 8; kb++) {
        float4 ra[8], rb[8];
#pragma unroll
        for (int q = 0; q < 8; q++) {
            int fidx = t * 8 + q;
            int row = fidx >> 4;
            int kq = (fidx & 15) << 2;
            ra[q] = *(const float4*)(A + (size_t)(m0 + row) * NHID + kb * 64 + kq);
            rb[q] = *(const float4*)(W + (size_t)row * NHID + kb * 64 + kq);
        }
        __syncthreads();
#pragma unroll
        for (int q = 0; q < 8; q++) {
            int fidx = t * 8 + q;
            int row = fidx >> 4;
            int kq = (fidx & 15) << 2;
            uint32_t off = SWZ128((uint32_t)(row * 128 + kq * 2));
            float4 a = ra[q], b = rb[q];
            *(uint2*)(p + SM_AHI + off) = make_uint2(pack_bf2(a.x, a.y), pack_bf2(a.z, a.w));
            *(uint2*)(p + SM_ALO + off) = make_uint2(pack_bf2(bf_residual(a.x), bf_residual(a.y)),
                                                     pack_bf2(bf_residual(a.z), bf_residual(a.w)));
            *(uint2*)(p + SM_BHI + off) = make_uint2(pack_bf2(b.x, b.y), pack_bf2(b.z, b.w));
            *(uint2*)(p + SM_BLO + off) = make_uint2(pack_bf2(bf_residual(b.x), bf_residual(b.y)),
                                                     pack_bf2(bf_residual(b.z), bf_residual(b.w)));
        }
        __syncthreads();

#pragma unroll
        for (int ks = 0; ks < 4; ks++) {
            int kb2 = ks * 32;
            uint32_t ah[2][4], al[2][4];
#pragma unroll
            for (int mt = 0; mt < 2; mt++) {
                uint32_t off = SWZ128((uint32_t)(((m0w + mt * 16 + a_row) << 7) + kb2 + a_kb));
                LDM4(ah[mt], sb + SM_AHI + off);
                LDM4(al[mt], sb + SM_ALO + off);
            }
#pragma unroll
            for (int half = 0; half < 2; half++) {
                uint32_t bh[2][4], bl[2][4];
#pragma unroll
                for (int g = 0; g < 2; g++) {
                    uint32_t off = SWZ128((uint32_t)(((n0w + half * 32 + g * 16 + b_row) << 7) + kb2 + b_kb));
                    LDM4(bh[g], sb + SM_BHI + off);
                    LDM4(bl[g], sb + SM_BLO + off);
                }
#pragma unroll
                for (int mt = 0; mt < 2; mt++)
#pragma unroll
                    for (int n4 = 0; n4 < 4; n4++) {
                        int g = n4 >> 1, wch = (n4 & 1) * 2;
                        float* cc = c[mt][half * 4 + n4];
                        MMA16816(cc, ah[mt], bh[g][wch], bh[g][wch + 1]);
                        MMA16816(cc, ah[mt], bl[g][wch], bl[g][wch + 1]);
                        MMA16816(cc, al[mt], bh[g][wch], bh[g][wch + 1]);
                    }
            }
        }
    }
    __syncthreads();

    float* bias_s = (float*)(p + SM_BIAS);
    float* norm_s = (float*)(p + SM_NORM);
    float* npart  = (float*)(p + SM_NPART);
    float* stg    = (float*)(p + SM_OPND);

    float rs[4] = {0.0f, 0.0f, 0.0f, 0.0f};
#pragma unroll
    for (int nt = 0; nt < 8; nt++) {
        int col = n0w + nt * 8 + 2 * (lane & 3);
        float b0 = bias_s[col], b1 = bias_s[col + 1];
#pragma unroll
        for (int mt = 0; mt < 2; mt++) {
            c[mt][nt][0] += b0; c[mt][nt][1] += b1;
            c[mt][nt][2] += b0; c[mt][nt][3] += b1;
            rs[mt * 2 + 0] += c[mt][nt][0] * c[mt][nt][0] + c[mt][nt][1] * c[mt][nt][1];
            rs[mt * 2 + 1] += c[mt][nt][2] * c[mt][nt][2] + c[mt][nt][3] * c[mt][nt][3];
            int row = m0w + mt * 16 + (lane >> 2);
            *(float2*)(stg + row * STG_STRIDE + col) = make_float2(c[mt][nt][0], c[mt][nt][1]);
            *(float2*)(stg + (row + 8) * STG_STRIDE + col) = make_float2(c[mt][nt][2], c[mt][nt][3]);
        }
    }
#pragma unroll
    for (int i = 0; i < 4; i++) {
        rs[i] += __shfl_xor_sync(0xffffffffu, rs[i], 1);
        rs[i] += __shfl_xor_sync(0xffffffffu, rs[i], 2);
    }
    if ((lane & 3) == 0) {
        int rbase = m0w + (lane >> 2);
#pragma unroll
        for (int i = 0; i < 4; i++)
            npart[(rbase + i * 8) * 2 + warp_n] = rs[i];
    }
    __syncthreads();

    if (t < 128) {
        float nrm = sqrtf(npart[t * 2] + npart[t * 2 + 1]);
        norm_s[t] = nrm;
        int grow = m0 + t;
        float om = 1.0f - nrm;
        out[OFF_RED + grow] = om * om;
        out[OFF_KLD + grow] = kld;
    }
    __syncthreads();

    float4* muv = (float4*)(out + OFF_MU + (size_t)m0 * NLAT);
#pragma unroll
    for (int j = 0; j < 16; j++) {
        int idx = t * 16 + j;
        int r = idx >> 5;
        int c4 = idx & 31;
        float4 v = *(float4*)(stg + r * STG_STRIDE + c4 * 4);
        float nrm = norm_s[r];
        v.x /= nrm; v.y /= nrm; v.z /= nrm; v.w /= nrm;
        muv[r * 32 + c4] = v;
    }
}

// ---------------- Kernel 2: vMF weight rejection sampler ----------------
__global__ __launch_bounds__(256) void wsample_kernel(Keys2 K, float A1, float A2,
                                                      float Xc, float Cc)
{
    int i = blockIdx.x * 256 + threadIdx.x;
    if (i >= NROWS) return;
    uint32_t ui = (uint32_t)i;
    float w = 0.0f;
#pragma unroll 1
    for (int t = 0; t < TMAX; t++) {
        uint32_t ga0, ga1, gb0, gb1;
        tf2x32(K.ka[t][0], K.ka[t][1], 0u, ui, ga0, ga1);
        tf2x32(K.kb[t][0], K.kb[t][1], 0u, ui, gb0, gb1);
        float lga = log_gamma_one(ga0, ga1);
        float lgb = log_gamma_one(gb0, gb1);
        float mx = fmaxf(lga, lgb);
        float gA = expf(__fsub_rn(lga, mx));
        float gB = expf(__fsub_rn(lgb, mx));
        float z = __fdiv_rn(gA, __fadd_rn(gA, gB));

        float wn = __fdiv_rn(__fsub_rn(1.0f, __fmul_rn(A1, z)),
                             __fsub_rn(1.0f, __fmul_rn(A2, z)));
        float u = u01(rbits(K.ku[t][0], K.ku[t][1], ui));
        float lhs = __fsub_rn(
            __fadd_rn(__fmul_rn(50.0f, wn),
                      __fmul_rn(127.0f, logf(__fsub_rn(1.0f, __fmul_rn(Xc, wn))))),
            Cc);
        if (lhs >= logf(u)) { w = wn; break; }
    }
    g_w[i] = w;
}

// ---------------- Kernel V1: bulk normal generation (mu-independent) ----------
__global__ __launch_bounds__(256) void vgen_kernel(uint32_t kv0, uint32_t kv1)
{
    uint32_t base = blockIdx.x * 1024u + threadIdx.x;
#pragma unroll
    for (int k = 0; k < 4; k++) {
        uint32_t i = base + k * 256u;
        g_v[i] = jax_normal(rbits(kv0, kv1, i));
    }
}

// ---------------- Kernel V2: orthogonalize + scale (mem-bound) ----------------
__global__ __launch_bounds__(256) void vfin_kernel(
    const float* __restrict__ mu, float* __restrict__ vecs,
    uint32_t kn0, uint32_t kn1)
{
    int wid = threadIdx.x >> 5;
    int lane = threadIdx.x & 31;
    int b = blockIdx.x * 2 + (wid >> 2);     // 4 warps share one b (mu row reuse)
    int n = wid & 3;
    int r = n * NB + b;                       // sample-row index (matches RNG counters)
    const float* murow = mu + (size_t)b * NLAT;
    const float* vrow = g_v + (size_t)r * NLAT;

    float m[4], v[4];
#pragma unroll
    for (int q = 0; q < 4; q++) {
        int j = lane + q * 32;
        m[q] = __ldg(&murow[j]);
        v[q] = vrow[j];
    }

    float dot = 0.0f, msq = 0.0f;
#pragma unroll
    for (int q = 0; q < 4; q++) { dot += m[q] * v[q]; msq += m[q] * m[q]; }
#pragma unroll
    for (int o = 16; o; o >>= 1) {
        dot += __shfl_xor_sync(0xffffffffu, dot, o);
        msq += __shfl_xor_sync(0xffffffffu, msq, o);
    }
    float mu_n = sqrtf(msq);
    float tproj = dot / mu_n;

    float og[4];
    float osq = 0.0f;
#pragma unroll
    for (int q = 0; q < 4; q++) { og[q] = v[q] - m[q] * tproj; osq += og[q] * og[q]; }
#pragma unroll
    for (int o = 16; o; o >>= 1) osq += __shfl_xor_sync(0xffffffffu, osq, o);
    float onorm = sqrtf(osq);

    float w = 0.0f, nn = 0.0f;
    if (lane == 0) {
        w = g_w[r];
        nn = 1.0f + u01(rbits(kn0, kn1, (uint32_t)r));
    }
    w = __shfl_sync(0xffffffffu, w, 0);
    nn = __shfl_sync(0xffffffffu, nn, 0);
    float s = sqrtf(1.0f - w * w);

    float* outrow = vecs + (size_t)r * NLAT;
#pragma unroll
    for (int q = 0; q < 4; q++) {
        int j = lane + q * 32;
        float vo = og[q] / onorm;
        outrow[j] = (vo * s + m[q] * w) * nn;
    }
}

// ---------------- Host ----------------
static double host_log_iv(double nu, double k) {
    const int M = 300;
    double logt[M];
    double mx = -1e300;
    for (int m = 0; m < M; m++) {
        double tv = (2.0 * m + nu) * log(k / 2.0) - lgamma(m + 1.0) - lgamma(m + nu + 1.0);
        logt[m] = tv;
        if (tv > mx) mx = tv;
    }
    double s = 0.0;
    for (int m = 0; m < M; m++) s += exp(logt[m] - mx);
    return mx + log(s);
}

extern "C" void kernel_launch(void* const* d_in, const int* in_sizes, int n_in,
                              void* d_out, int out_size)
{
    const float* lat = (const float*)d_in[0];
    const float* Wm  = (const float*)d_in[1];
    const float* bm  = (const float*)d_in[2];
    float* out = (float*)d_out;

    const double dd = 127.0, kap = 50.0;
    double b = dd / (sqrt(4.0 * kap * kap + dd * dd) + 2.0 * kap);
    double x = (1.0 - b) / (1.0 + b);
    double c = kap * x + dd * log(1.0 - x * x);
    float A1 = (float)(1.0 + b), A2 = (float)(1.0 - b);
    float Xc = (float)x, Cc = (float)c;

    const double D = 128.0;
    double liv0 = host_log_iv(D / 2.0, kap);
    double liv1 = host_log_iv(D / 2.0 + 1.0, kap);
    double ratio = exp(liv1 - liv0);
    double a_ = D / (2.0 * kap);
    double vmf = kap * (ratio + a_ - a_) + D * log(kap) / 2.0 - liv0
               - lgamma(D / 2.0 + 1.0) - D * log(2.0) / 2.0;
    float kld = (float)(vmf + log(2.0 / 1.0));

    uint32_t kw0, kw1, kv0, kv1, kn0, kn1;
    tf2x32(0u, 1u, 0u, 0u, kw0, kw1);
    tf2x32(0u, 1u, 0u, 1u, kv0, kv1);
    tf2x32(0u, 1u, 0u, 2u, kn0, kn1);

    Keys2 K;
    uint32_t c0 = kw0, c1 = kw1;
    for (int t = 0; t < TMAX; t++) {
        uint32_t nk0, nk1, kz0, kz1, ku0, ku1;
        tf2x32(c0, c1, 0u, 0u, nk0, nk1);
        tf2x32(c0, c1, 0u, 1u, kz0, kz1);
        tf2x32(c0, c1, 0u, 2u, ku0, ku1);
        tf2x32(kz0, kz1, 0u, 0u, K.ka[t][0], K.ka[t][1]);
        tf2x32(kz0, kz1, 0u, 1u, K.kb[t][0], K.kb[t][1]);
        K.ku[t][0] = ku0; K.ku[t][1] = ku1;
        c0 = nk0; c1 = nk1;
    }

    // one-time side-stream/event setup (outside capture: correctness run comes first)
    static cudaStream_t s1 = nullptr;
    static cudaEvent_t eFork = nullptr, eSide = nullptr;
    if (!s1) {
        cudaStreamCreateWithFlags(&s1, cudaStreamNonBlocking);
        cudaEventCreateWithFlags(&eFork, cudaEventDisableTiming);
        cudaEventCreateWithFlags(&eSide, cudaEventDisableTiming);
        cudaFuncSetAttribute(gemm_mu_kernel,
                             cudaFuncAttributeMaxDynamicSharedMemorySize, SM_DYN);
    }

    // fork: s1 runs RNG-only work concurrently with the GEMM on the main stream
    cudaEventRecord(eFork, 0);
    cudaStreamWaitEvent(s1, eFork, 0);
    wsample_kernel<<<NROWS / 256, 256, 0, s1>>>(K, A1, A2, Xc, Cc);
    vgen_kernel<<<NVTOT / 1024, 256, 0, s1>>>(kv0, kv1);
    cudaEventRecord(eSide, s1);

    gemm_mu_kernel<<<NB / 128, 256, SM_DYN>>>(lat, Wm, bm, out, kld);

    // join, then the memory-bound finisher
    cudaStreamWaitEvent(0, eSide, 0);
    vfin_kernel<<<NB / 2, 256>>>(out + OFF_MU, out + OFF_VECS, kn0, kn1);
}

// round 12
// speedup vs baseline: 1.2912x; 1.0732x over previous
#include <cuda_runtime.h>
#include <cuda_bf16.h>
#include <cstdint>
#include <math.h>

#define NB    65536
#define NHID  512
#define NLAT  128
#define NS    4
#define NROWS (NS*NB)          // 262144
#define NVTOT (NROWS*NLAT)     // 33554432
#define TMAX  32

#define OFF_VECS 0
#define OFF_KLD  (33554432)
#define OFF_MU   (OFF_KLD + NB)
#define OFF_RED  (OFF_MU + NB*NLAT)

// scratch (no cudaMalloc allowed)
__device__ float g_w[NROWS];
__device__ float g_v[NVTOT];
// pre-converted, pre-swizzled W images: per chunk kb (64 K): [16KB hi | 16KB lo]
__device__ __align__(128) unsigned char g_bcvt[8 * 32768];

struct Keys2 {
    uint32_t ka[TMAX][2];
    uint32_t kb[TMAX][2];
    uint32_t ku[TMAX][2];
};

// ---------------- Threefry-2x32 (JAX exact) ----------------
__host__ __device__ __forceinline__ void tf2x32(uint32_t k0, uint32_t k1,
                                                uint32_t x0, uint32_t x1,
                                                uint32_t& o0, uint32_t& o1) {
    uint32_t ks2 = k0 ^ k1 ^ 0x1BD11BDAu;
    x0 += k0; x1 += k1;
#define TFR(r) { x0 += x1; x1 = (x1 << (r)) | (x1 >> (32 - (r))); x1 ^= x0; }
    TFR(13) TFR(15) TFR(26) TFR(6)   x0 += k1;  x1 += ks2 + 1u;
    TFR(17) TFR(29) TFR(16) TFR(24)  x0 += ks2; x1 += k0 + 2u;
    TFR(13) TFR(15) TFR(26) TFR(6)   x0 += k0;  x1 += k1 + 3u;
    TFR(17) TFR(29) TFR(16) TFR(24)  x0 += k1;  x1 += ks2 + 4u;
    TFR(13) TFR(15) TFR(26) TFR(6)   x0 += ks2; x1 += k0 + 5u;
#undef TFR
    o0 = x0; o1 = x1;
}

__device__ __forceinline__ uint32_t rbits(uint32_t k0, uint32_t k1, uint32_t idx) {
    uint32_t o0, o1;
    tf2x32(k0, k1, 0u, idx, o0, o1);
    return o0 ^ o1;
}

__device__ __forceinline__ float u01(uint32_t bits) {
    return __uint_as_float((bits >> 9) | 0x3f800000u) - 1.0f;
}

// XLA ErfInv32 — exact constants & op order
__device__ __forceinline__ float erfinv_xla(float x) {
    float w = -log1pf(-__fmul_rn(x, x));
    float p;
    if (w < 5.0f) {
        w = __fsub_rn(w, 2.5f);
        p = 2.81022636e-08f;
        p = __fadd_rn(3.43273939e-07f,  __fmul_rn(p, w));
        p = __fadd_rn(-3.5233877e-06f,  __fmul_rn(p, w));
        p = __fadd_rn(-4.39150654e-06f, __fmul_rn(p, w));
        p = __fadd_rn(0.00021858087f,   __fmul_rn(p, w));
        p = __fadd_rn(-0.00125372503f,  __fmul_rn(p, w));
        p = __fadd_rn(-0.00417768164f,  __fmul_rn(p, w));
        p = __fadd_rn(0.246640727f,     __fmul_rn(p, w));
        p = __fadd_rn(1.50140941f,      __fmul_rn(p, w));
    } else {
        w = __fsub_rn(sqrtf(w), 3.0f);
        p = -0.000200214257f;
        p = __fadd_rn(0.000100950558f,  __fmul_rn(p, w));
        p = __fadd_rn(0.00134934322f,   __fmul_rn(p, w));
        p = __fadd_rn(-0.00367342844f,  __fmul_rn(p, w));
        p = __fadd_rn(0.00573950773f,   __fmul_rn(p, w));
        p = __fadd_rn(-0.0076224613f,   __fmul_rn(p, w));
        p = __fadd_rn(0.00943887047f,   __fmul_rn(p, w));
        p = __fadd_rn(1.00167406f,      __fmul_rn(p, w));
        p = __fadd_rn(2.83297682f,      __fmul_rn(p, w));
    }
    return __fmul_rn(p, x);
}

__device__ __forceinline__ float jax_normal(uint32_t bits) {
    const float lo = -0.99999994f;
    float f = u01(bits);
    float u = __fadd_rn(__fmul_rn(f, 2.0f), lo);
    u = fmaxf(lo, u);
    return __fmul_rn(1.41421356237f, erfinv_xla(u));
}

// jax _gamma_one(key, alpha=63.5, log_space=True) — exact chain
__device__ __forceinline__ float log_gamma_one(uint32_t gk0, uint32_t gk1) {
    const float one_third = 0.33333334f;
    float dg = __fsub_rn(63.5f, one_third);
    float cg = __fdiv_rn(one_third, sqrtf(dg));

    uint32_t key0, key1;
    tf2x32(gk0, gk1, 0u, 0u, key0, key1);

    while (true) {
        uint32_t nk0, nk1, xk0, xk1, Uk0, Uk1;
        tf2x32(key0, key1, 0u, 0u, nk0, nk1);
        tf2x32(key0, key1, 0u, 1u, xk0, xk1);
        tf2x32(key0, key1, 0u, 2u, Uk0, Uk1);
        key0 = nk0; key1 = nk1;

        float x, v;
        uint32_t cx0 = xk0, cx1 = xk1;
        while (true) {
            uint32_t s0, s1;
            tf2x32(cx0, cx1, 0u, 1u, s0, s1);
            x = jax_normal(rbits(s0, s1, 0u));
            v = __fadd_rn(1.0f, __fmul_rn(x, cg));
            if (v > 0.0f) break;
            uint32_t n0, n1;
            tf2x32(cx0, cx1, 0u, 0u, n0, n1);
            cx0 = n0; cx1 = n1;
        }

        float X = __fmul_rn(x, x);
        float V = __fmul_rn(__fmul_rn(v, v), v);
        float U = u01(rbits(Uk0, Uk1, 0u));

        float sq = __fsub_rn(1.0f, __fmul_rn(0.0331f, __fmul_rn(X, X)));
        bool cont;
        if (U < sq) {
            cont = false;
        } else {
            float th = __fadd_rn(__fmul_rn(X, 0.5f),
                                 __fmul_rn(dg, __fadd_rn(__fsub_rn(1.0f, V), logf(V))));
            cont = (logf(U) >= th);
        }
        if (!cont) return __fadd_rn(logf(V), logf(dg));
    }
}

// ================= mma.sync helpers =================
__device__ __forceinline__ uint32_t smem_u32(const void* p) {
    uint32_t a;
    asm("{ .reg .u64 t; cvta.to.shared.u64 t, %1; cvt.u32.u64 %0, t; }"
        : "=r"(a) : "l"(p));
    return a;
}
#define SWZ128(o) ((o) ^ (((o) >> 3) & 0x70))

#define LDM4(r, addr)                                                              \
    asm volatile("ldmatrix.sync.aligned.m8n8.x4.shared.b16 {%0,%1,%2,%3}, [%4];"   \
        : "=r"((r)[0]), "=r"((r)[1]), "=r"((r)[2]), "=r"((r)[3]) : "r"(addr))

#define MMA16816(c, a, b0, b1)                                                     \
    asm volatile("mma.sync.aligned.m16n8k16.row.col.f32.bf16.bf16.f32 "            \
        "{%0,%1,%2,%3}, {%4,%5,%6,%7}, {%8,%9}, {%0,%1,%2,%3};"                    \
        : "+f"((c)[0]), "+f"((c)[1]), "+f"((c)[2]), "+f"((c)[3])                   \
        : "r"((a)[0]), "r"((a)[1]), "r"((a)[2]), "r"((a)[3]), "r"(b0), "r"(b1))

#define CPASYNC16(dst, src)                                                        \
    asm volatile("cp.async.cg.shared.global [%0], [%1], 16;" :: "r"(dst), "l"(src))
#define CPCOMMIT()  asm volatile("cp.async.commit_group;" ::: "memory")
#define CPWAIT0()   asm volatile("cp.async.wait_group 0;" ::: "memory")

__device__ __forceinline__ uint32_t pack_bf2(float a, float b) {
    __nv_bfloat162 t = __floats2bfloat162_rn(a, b);
    return *reinterpret_cast<uint32_t*>(&t);
}

// smem layout (byte offsets from 1024-aligned base)
#define SM_BIAS   0
#define SM_NORM   512
#define SM_NPART  1024
#define SM_AHI    2048
#define SM_ALO    18432
#define SM_BHI    34816
#define SM_BLO    51200
#define STG_STRIDE 132
#define SM_DYN    (2048 + 128*STG_STRIDE*4 + 1024)   // 70656 (covers operands)

// ---------------- Kernel 0: pre-convert + pre-swizzle W ----------------
__global__ __launch_bounds__(256) void convW_kernel(const float* __restrict__ W)
{
    int idx0 = (blockIdx.x * 256 + threadIdx.x) * 8;
#pragma unroll
    for (int q = 0; q < 8; q++) {
        int idx = idx0 + q;                 // 0..65535
        int row = idx >> 9;                 // 0..127
        int k = idx & 511;
        int kb = k >> 6;
        int k2 = k & 63;
        float w = W[idx];
        __nv_bfloat16 hi = __float2bfloat16_rn(w);
        float hif = __bfloat162float(hi);
        __nv_bfloat16 lo = __float2bfloat16_rn(__fsub_rn(w, hif));
        uint32_t off = kb * 32768u + SWZ128((uint32_t)(row * 128 + k2 * 2));
        *(__nv_bfloat16*)(g_bcvt + off) = hi;
        *(__nv_bfloat16*)(g_bcvt + off + 16384u) = lo;
    }
}

// ---------------- Kernel 1: mma.sync split-bf16 SGEMM + epilogue ----------------
__global__ __launch_bounds__(256) void gemm_mu_kernel(
    const float* __restrict__ A,
    const float* __restrict__ bias,
    float* __restrict__ out, float kld)
{
    extern __shared__ char dsm[];
    char* p = (char*)(((uintptr_t)dsm + 1023) & ~(uintptr_t)1023);
    uint32_t sb = smem_u32(p);

    int t = threadIdx.x;
    int wid = t >> 5;
    int lane = t & 31;
    int m0 = blockIdx.x * 128;

    int warp_m = wid & 3;
    int warp_n = wid >> 2;
    int m0w = warp_m * 32;
    int n0w = warp_n * 64;

    if (t < 128) *(float*)(p + SM_BIAS + t * 4) = bias[t];

    float c[2][8][4];
#pragma unroll
    for (int mt = 0; mt < 2; mt++)
#pragma unroll
        for (int nt = 0; nt < 8; nt++)
#pragma unroll
            for (int q = 0; q < 4; q++) c[mt][nt][q] = 0.0f;

    int a_row = (lane & 7) + ((lane >> 3) & 1) * 8;
    int a_kb  = (lane >> 4) * 16;
    int b_row = (lane & 7) + (lane >> 4) * 8;
    int b_kb  = ((lane >> 3) & 1) * 16;

    for (int kb = 0; kb < 8; kb++) {
        // prefetch A chunk into registers
        float4 ra[8];
#pragma unroll
        for (int q = 0; q < 8; q++) {
            int fidx = t * 8 + q;
            int row = fidx >> 4;
            int kq = (fidx & 15) << 2;
            ra[q] = *(const float4*)(A + (size_t)(m0 + row) * NHID + kb * 64 + kq);
        }
        __syncthreads();   // prev chunk's smem reads complete

        // B chunk: byte-linear cp.async of pre-swizzled image (32KB)
        {
            const unsigned char* src = g_bcvt + (size_t)kb * 32768u;
#pragma unroll
            for (int j = 0; j < 8; j++) {
                uint32_t o = (uint32_t)(t + j * 256) * 16u;
                CPASYNC16(sb + SM_BHI + o, src + o);
            }
            CPCOMMIT();
        }

        // A: hi/lo split, cheap residual recovery via bit ops
#pragma unroll
        for (int q = 0; q < 8; q++) {
            int fidx = t * 8 + q;
            int row = fidx >> 4;
            int kq = (fidx & 15) << 2;
            uint32_t off = SWZ128((uint32_t)(row * 128 + kq * 2));
            float4 a = ra[q];
            uint32_t h01 = pack_bf2(a.x, a.y);
            uint32_t h23 = pack_bf2(a.z, a.w);
            float hx = __uint_as_float(h01 << 16);
            float hy = __uint_as_float(h01 & 0xFFFF0000u);
            float hz = __uint_as_float(h23 << 16);
            float hw = __uint_as_float(h23 & 0xFFFF0000u);
            uint32_t l01 = pack_bf2(__fsub_rn(a.x, hx), __fsub_rn(a.y, hy));
            uint32_t l23 = pack_bf2(__fsub_rn(a.z, hz), __fsub_rn(a.w, hw));
            *(uint2*)(p + SM_AHI + off) = make_uint2(h01, h23);
            *(uint2*)(p + SM_ALO + off) = make_uint2(l01, l23);
        }
        CPWAIT0();
        __syncthreads();

#pragma unroll
        for (int ks = 0; ks < 4; ks++) {
            int kb2 = ks * 32;
            uint32_t ah[2][4], al[2][4];
#pragma unroll
            for (int mt = 0; mt < 2; mt++) {
                uint32_t off = SWZ128((uint32_t)(((m0w + mt * 16 + a_row) << 7) + kb2 + a_kb));
                LDM4(ah[mt], sb + SM_AHI + off);
                LDM4(al[mt], sb + SM_ALO + off);
            }
#pragma unroll
            for (int half = 0; half < 2; half++) {
                uint32_t bh[2][4], bl[2][4];
#pragma unroll
                for (int g = 0; g < 2; g++) {
                    uint32_t off = SWZ128((uint32_t)(((n0w + half * 32 + g * 16 + b_row) << 7) + kb2 + b_kb));
                    LDM4(bh[g], sb + SM_BHI + off);
                    LDM4(bl[g], sb + SM_BLO + off);
                }
#pragma unroll
                for (int mt = 0; mt < 2; mt++)
#pragma unroll
                    for (int n4 = 0; n4 < 4; n4++) {
                        int g = n4 >> 1, wch = (n4 & 1) * 2;
                        float* cc = c[mt][half * 4 + n4];
                        MMA16816(cc, ah[mt], bh[g][wch], bh[g][wch + 1]);
                        MMA16816(cc, ah[mt], bl[g][wch], bl[g][wch + 1]);
                        MMA16816(cc, al[mt], bh[g][wch], bh[g][wch + 1]);
                    }
            }
        }
    }
    __syncthreads();

    float* bias_s = (float*)(p + SM_BIAS);
    float* norm_s = (float*)(p + SM_NORM);
    float* npart  = (float*)(p + SM_NPART);
    float* stg    = (float*)(p + SM_AHI);

    float rs[4] = {0.0f, 0.0f, 0.0f, 0.0f};
#pragma unroll
    for (int nt = 0; nt < 8; nt++) {
        int col = n0w + nt * 8 + 2 * (lane & 3);
        float b0 = bias_s[col], b1 = bias_s[col + 1];
#pragma unroll
        for (int mt = 0; mt < 2; mt++) {
            c[mt][nt][0] += b0; c[mt][nt][1] += b1;
            c[mt][nt][2] += b0; c[mt][nt][3] += b1;
            rs[mt * 2 + 0] += c[mt][nt][0] * c[mt][nt][0] + c[mt][nt][1] * c[mt][nt][1];
            rs[mt * 2 + 1] += c[mt][nt][2] * c[mt][nt][2] + c[mt][nt][3] * c[mt][nt][3];
            int row = m0w + mt * 16 + (lane >> 2);
            *(float2*)(stg + row * STG_STRIDE + col) = make_float2(c[mt][nt][0], c[mt][nt][1]);
            *(float2*)(stg + (row + 8) * STG_STRIDE + col) = make_float2(c[mt][nt][2], c[mt][nt][3]);
        }
    }
#pragma unroll
    for (int i = 0; i < 4; i++) {
        rs[i] += __shfl_xor_sync(0xffffffffu, rs[i], 1);
        rs[i] += __shfl_xor_sync(0xffffffffu, rs[i], 2);
    }
    if ((lane & 3) == 0) {
        int rbase = m0w + (lane >> 2);
#pragma unroll
        for (int i = 0; i < 4; i++)
            npart[(rbase + i * 8) * 2 + warp_n] = rs[i];
    }
    __syncthreads();

    if (t < 128) {
        float nrm = sqrtf(npart[t * 2] + npart[t * 2 + 1]);
        norm_s[t] = nrm;
        int grow = m0 + t;
        float om = 1.0f - nrm;
        out[OFF_RED + grow] = om * om;
        out[OFF_KLD + grow] = kld;
    }
    __syncthreads();

    float4* muv = (float4*)(out + OFF_MU + (size_t)m0 * NLAT);
#pragma unroll
    for (int j = 0; j < 16; j++) {
        int idx = t * 16 + j;
        int r = idx >> 5;
        int c4 = idx & 31;
        float4 v = *(float4*)(stg + r * STG_STRIDE + c4 * 4);
        float nrm = norm_s[r];
        v.x /= nrm; v.y /= nrm; v.z /= nrm; v.w /= nrm;
        muv[r * 32 + c4] = v;
    }
}

// ---------------- Kernel 2: vMF weight rejection sampler ----------------
__global__ __launch_bounds__(256) void wsample_kernel(Keys2 K, float A1, float A2,
                                                      float Xc, float Cc)
{
    int i = blockIdx.x * 256 + threadIdx.x;
    if (i >= NROWS) return;
    uint32_t ui = (uint32_t)i;
    float w = 0.0f;
#pragma unroll 1
    for (int t = 0; t < TMAX; t++) {
        uint32_t ga0, ga1, gb0, gb1;
        tf2x32(K.ka[t][0], K.ka[t][1], 0u, ui, ga0, ga1);
        tf2x32(K.kb[t][0], K.kb[t][1], 0u, ui, gb0, gb1);
        float lga = log_gamma_one(ga0, ga1);
        float lgb = log_gamma_one(gb0, gb1);
        float mx = fmaxf(lga, lgb);
        float gA = expf(__fsub_rn(lga, mx));
        float gB = expf(__fsub_rn(lgb, mx));
        float z = __fdiv_rn(gA, __fadd_rn(gA, gB));

        float wn = __fdiv_rn(__fsub_rn(1.0f, __fmul_rn(A1, z)),
                             __fsub_rn(1.0f, __fmul_rn(A2, z)));
        float u = u01(rbits(K.ku[t][0], K.ku[t][1], ui));
        float lhs = __fsub_rn(
            __fadd_rn(__fmul_rn(50.0f, wn),
                      __fmul_rn(127.0f, logf(__fsub_rn(1.0f, __fmul_rn(Xc, wn))))),
            Cc);
        if (lhs >= logf(u)) { w = wn; break; }
    }
    g_w[i] = w;
}

// ---------------- Kernel V1: bulk normal generation ----------
__global__ __launch_bounds__(256) void vgen_kernel(uint32_t kv0, uint32_t kv1)
{
    uint32_t i4 = (blockIdx.x * 256u + threadIdx.x) * 4u;
    float4 o;
    o.x = jax_normal(rbits(kv0, kv1, i4));
    o.y = jax_normal(rbits(kv0, kv1, i4 + 1u));
    o.z = jax_normal(rbits(kv0, kv1, i4 + 2u));
    o.w = jax_normal(rbits(kv0, kv1, i4 + 3u));
    *(float4*)(g_v + i4) = o;
}

// ---------------- Kernel V2: orthogonalize + scale (mem-bound) ----------------
__global__ __launch_bounds__(256) void vfin_kernel(
    const float* __restrict__ mu, float* __restrict__ vecs,
    uint32_t kn0, uint32_t kn1)
{
    int wid = threadIdx.x >> 5;
    int lane = threadIdx.x & 31;
    int b = blockIdx.x * 2 + (wid >> 2);     // 4 warps share one b
    int n = wid & 3;
    int r = n * NB + b;
    const float* murow = mu + (size_t)b * NLAT;
    const float* vrow = g_v + (size_t)r * NLAT;

    float4 m4 = __ldg((const float4*)(murow + lane * 4));
    float4 v4 = *(const float4*)(vrow + lane * 4);

    float dot = m4.x * v4.x + m4.y * v4.y + m4.z * v4.z + m4.w * v4.w;
    float msq = m4.x * m4.x + m4.y * m4.y + m4.z * m4.z + m4.w * m4.w;
#pragma unroll
    for (int o = 16; o; o >>= 1) {
        dot += __shfl_xor_sync(0xffffffffu, dot, o);
        msq += __shfl_xor_sync(0xffffffffu, msq, o);
    }
    float mu_n = sqrtf(msq);
    float tproj = dot / mu_n;

    float4 og;
    og.x = v4.x - m4.x * tproj;
    og.y = v4.y - m4.y * tproj;
    og.z = v4.z - m4.z * tproj;
    og.w = v4.w - m4.w * tproj;
    float osq = og.x * og.x + og.y * og.y + og.z * og.z + og.w * og.w;
#pragma unroll
    for (int o = 16; o; o >>= 1) osq += __shfl_xor_sync(0xffffffffu, osq, o);
    float onorm = sqrtf(osq);

    float w = 0.0f, nn = 0.0f;
    if (lane == 0) {
        w = g_w[r];
        nn = 1.0f + u01(rbits(kn0, kn1, (uint32_t)r));
    }
    w = __shfl_sync(0xffffffffu, w, 0);
    nn = __shfl_sync(0xffffffffu, nn, 0);
    float s = sqrtf(1.0f - w * w);

    float4 ov;
    ov.x = (og.x / onorm * s + m4.x * w) * nn;
    ov.y = (og.y / onorm * s + m4.y * w) * nn;
    ov.z = (og.z / onorm * s + m4.z * w) * nn;
    ov.w = (og.w / onorm * s + m4.w * w) * nn;
    *(float4*)(vecs + (size_t)r * NLAT + lane * 4) = ov;
}

// ---------------- Host ----------------
static double host_log_iv(double nu, double k) {
    const int M = 300;
    double logt[M];
    double mx = -1e300;
    for (int m = 0; m < M; m++) {
        double tv = (2.0 * m + nu) * log(k / 2.0) - lgamma(m + 1.0) - lgamma(m + nu + 1.0);
        logt[m] = tv;
        if (tv > mx) mx = tv;
    }
    double s = 0.0;
    for (int m = 0; m < M; m++) s += exp(logt[m] - mx);
    return mx + log(s);
}

extern "C" void kernel_launch(void* const* d_in, const int* in_sizes, int n_in,
                              void* d_out, int out_size)
{
    const float* lat = (const float*)d_in[0];
    const float* Wm  = (const float*)d_in[1];
    const float* bm  = (const float*)d_in[2];
    float* out = (float*)d_out;

    const double dd = 127.0, kap = 50.0;
    double b = dd / (sqrt(4.0 * kap * kap + dd * dd) + 2.0 * kap);
    double x = (1.0 - b) / (1.0 + b);
    double c = kap * x + dd * log(1.0 - x * x);
    float A1 = (float)(1.0 + b), A2 = (float)(1.0 - b);
    float Xc = (float)x, Cc = (float)c;

    const double D = 128.0;
    double liv0 = host_log_iv(D / 2.0, kap);
    double liv1 = host_log_iv(D / 2.0 + 1.0, kap);
    double ratio = exp(liv1 - liv0);
    double a_ = D / (2.0 * kap);
    double vmf = kap * (ratio + a_ - a_) + D * log(kap) / 2.0 - liv0
               - lgamma(D / 2.0 + 1.0) - D * log(2.0) / 2.0;
    float kld = (float)(vmf + log(2.0 / 1.0));

    uint32_t kw0, kw1, kv0, kv1, kn0, kn1;
    tf2x32(0u, 1u, 0u, 0u, kw0, kw1);
    tf2x32(0u, 1u, 0u, 1u, kv0, kv1);
    tf2x32(0u, 1u, 0u, 2u, kn0, kn1);

    Keys2 K;
    uint32_t c0 = kw0, c1 = kw1;
    for (int t = 0; t < TMAX; t++) {
        uint32_t nk0, nk1, kz0, kz1, ku0, ku1;
        tf2x32(c0, c1, 0u, 0u, nk0, nk1);
        tf2x32(c0, c1, 0u, 1u, kz0, kz1);
        tf2x32(c0, c1, 0u, 2u, ku0, ku1);
        tf2x32(kz0, kz1, 0u, 0u, K.ka[t][0], K.ka[t][1]);
        tf2x32(kz0, kz1, 0u, 1u, K.kb[t][0], K.kb[t][1]);
        K.ku[t][0] = ku0; K.ku[t][1] = ku1;
        c0 = nk0; c1 = nk1;
    }

    static cudaStream_t s1 = nullptr;
    static cudaEvent_t eFork = nullptr, eSide = nullptr;
    if (!s1) {
        cudaStreamCreateWithFlags(&s1, cudaStreamNonBlocking);
        cudaEventCreateWithFlags(&eFork, cudaEventDisableTiming);
        cudaEventCreateWithFlags(&eSide, cudaEventDisableTiming);
        cudaFuncSetAttribute(gemm_mu_kernel,
                             cudaFuncAttributeMaxDynamicSharedMemorySize, SM_DYN);
    }

    // fork: RNG-only work on s1, GEMM path on main stream
    cudaEventRecord(eFork, 0);
    cudaStreamWaitEvent(s1, eFork, 0);
    wsample_kernel<<<NROWS / 256, 256, 0, s1>>>(K, A1, A2, Xc, Cc);
    vgen_kernel<<<NVTOT / 1024, 256, 0, s1>>>(kv0, kv1);
    cudaEventRecord(eSide, s1);

    convW_kernel<<<32, 256>>>(Wm);
    gemm_mu_kernel<<<NB / 128, 256, SM_DYN>>>(lat, bm, out, kld);

    cudaStreamWaitEvent(0, eSide, 0);
    vfin_kernel<<<NB / 2, 256>>>(out + OFF_MU, out + OFF_VECS, kn0, kn1);
}

// round 13
// speedup vs baseline: 1.3941x; 1.0797x over previous
#include <cuda_runtime.h>
#include <cuda_bf16.h>
#include <cstdint>
#include <math.h>

#define NB    65536
#define NHID  512
#define NLAT  128
#define NS    4
#define NROWS (NS*NB)          // 262144
#define TMAX  32

#define OFF_VECS 0
#define OFF_KLD  (33554432)
#define OFF_MU   (OFF_KLD + NB)
#define OFF_RED  (OFF_MU + NB*NLAT)

// scratch (no cudaMalloc allowed)
__device__ float g_w[NROWS];
// pre-converted, pre-swizzled W images: per chunk kb (64 K): [16KB hi | 16KB lo]
__device__ __align__(128) unsigned char g_bcvt[8 * 32768];

struct Keys2 {
    uint32_t ka[TMAX][2];
    uint32_t kb[TMAX][2];
    uint32_t ku[TMAX][2];
};

// ---------------- Threefry-2x32 (JAX exact) ----------------
__host__ __device__ __forceinline__ void tf2x32(uint32_t k0, uint32_t k1,
                                                uint32_t x0, uint32_t x1,
                                                uint32_t& o0, uint32_t& o1) {
    uint32_t ks2 = k0 ^ k1 ^ 0x1BD11BDAu;
    x0 += k0; x1 += k1;
#define TFR(r) { x0 += x1; x1 = (x1 << (r)) | (x1 >> (32 - (r))); x1 ^= x0; }
    TFR(13) TFR(15) TFR(26) TFR(6)   x0 += k1;  x1 += ks2 + 1u;
    TFR(17) TFR(29) TFR(16) TFR(24)  x0 += ks2; x1 += k0 + 2u;
    TFR(13) TFR(15) TFR(26) TFR(6)   x0 += k0;  x1 += k1 + 3u;
    TFR(17) TFR(29) TFR(16) TFR(24)  x0 += k1;  x1 += ks2 + 4u;
    TFR(13) TFR(15) TFR(26) TFR(6)   x0 += ks2; x1 += k0 + 5u;
#undef TFR
    o0 = x0; o1 = x1;
}

__device__ __forceinline__ uint32_t rbits(uint32_t k0, uint32_t k1, uint32_t idx) {
    uint32_t o0, o1;
    tf2x32(k0, k1, 0u, idx, o0, o1);
    return o0 ^ o1;
}

__device__ __forceinline__ float u01(uint32_t bits) {
    return __uint_as_float((bits >> 9) | 0x3f800000u) - 1.0f;
}

// XLA ErfInv32 — exact constants & op order
__device__ __forceinline__ float erfinv_xla(float x) {
    float w = -log1pf(-__fmul_rn(x, x));
    float p;
    if (w < 5.0f) {
        w = __fsub_rn(w, 2.5f);
        p = 2.81022636e-08f;
        p = __fadd_rn(3.43273939e-07f,  __fmul_rn(p, w));
        p = __fadd_rn(-3.5233877e-06f,  __fmul_rn(p, w));
        p = __fadd_rn(-4.39150654e-06f, __fmul_rn(p, w));
        p = __fadd_rn(0.00021858087f,   __fmul_rn(p, w));
        p = __fadd_rn(-0.00125372503f,  __fmul_rn(p, w));
        p = __fadd_rn(-0.00417768164f,  __fmul_rn(p, w));
        p = __fadd_rn(0.246640727f,     __fmul_rn(p, w));
        p = __fadd_rn(1.50140941f,      __fmul_rn(p, w));
    } else {
        w = __fsub_rn(sqrtf(w), 3.0f);
        p = -0.000200214257f;
        p = __fadd_rn(0.000100950558f,  __fmul_rn(p, w));
        p = __fadd_rn(0.00134934322f,   __fmul_rn(p, w));
        p = __fadd_rn(-0.00367342844f,  __fmul_rn(p, w));
        p = __fadd_rn(0.00573950773f,   __fmul_rn(p, w));
        p = __fadd_rn(-0.0076224613f,   __fmul_rn(p, w));
        p = __fadd_rn(0.00943887047f,   __fmul_rn(p, w));
        p = __fadd_rn(1.00167406f,      __fmul_rn(p, w));
        p = __fadd_rn(2.83297682f,      __fmul_rn(p, w));
    }
    return __fmul_rn(p, x);
}

__device__ __forceinline__ float jax_normal(uint32_t bits) {
    const float lo = -0.99999994f;
    float f = u01(bits);
    float u = __fadd_rn(__fmul_rn(f, 2.0f), lo);
    u = fmaxf(lo, u);
    return __fmul_rn(1.41421356237f, erfinv_xla(u));
}

// jax _gamma_one(key, alpha=63.5, log_space=True) — exact chain
__device__ __forceinline__ float log_gamma_one(uint32_t gk0, uint32_t gk1) {
    const float one_third = 0.33333334f;
    float dg = __fsub_rn(63.5f, one_third);
    float cg = __fdiv_rn(one_third, sqrtf(dg));

    uint32_t key0, key1;
    tf2x32(gk0, gk1, 0u, 0u, key0, key1);

    while (true) {
        uint32_t nk0, nk1, xk0, xk1, Uk0, Uk1;
        tf2x32(key0, key1, 0u, 0u, nk0, nk1);
        tf2x32(key0, key1, 0u, 1u, xk0, xk1);
        tf2x32(key0, key1, 0u, 2u, Uk0, Uk1);
        key0 = nk0; key1 = nk1;

        float x, v;
        uint32_t cx0 = xk0, cx1 = xk1;
        while (true) {
            uint32_t s0, s1;
            tf2x32(cx0, cx1, 0u, 1u, s0, s1);
            x = jax_normal(rbits(s0, s1, 0u));
            v = __fadd_rn(1.0f, __fmul_rn(x, cg));
            if (v > 0.0f) break;
            uint32_t n0, n1;
            tf2x32(cx0, cx1, 0u, 0u, n0, n1);
            cx0 = n0; cx1 = n1;
        }

        float X = __fmul_rn(x, x);
        float V = __fmul_rn(__fmul_rn(v, v), v);
        float U = u01(rbits(Uk0, Uk1, 0u));

        float sq = __fsub_rn(1.0f, __fmul_rn(0.0331f, __fmul_rn(X, X)));
        bool cont;
        if (U < sq) {
            cont = false;
        } else {
            float th = __fadd_rn(__fmul_rn(X, 0.5f),
                                 __fmul_rn(dg, __fadd_rn(__fsub_rn(1.0f, V), logf(V))));
            cont = (logf(U) >= th);
        }
        if (!cont) return __fadd_rn(logf(V), logf(dg));
    }
}

// ================= mma.sync helpers =================
__device__ __forceinline__ uint32_t smem_u32(const void* p) {
    uint32_t a;
    asm("{ .reg .u64 t; cvta.to.shared.u64 t, %1; cvt.u32.u64 %0, t; }"
        : "=r"(a) : "l"(p));
    return a;
}
#define SWZ128(o) ((o) ^ (((o) >> 3) & 0x70))

#define LDM4(r, addr)                                                              \
    asm volatile("ldmatrix.sync.aligned.m8n8.x4.shared.b16 {%0,%1,%2,%3}, [%4];"   \
        : "=r"((r)[0]), "=r"((r)[1]), "=r"((r)[2]), "=r"((r)[3]) : "r"(addr))

#define MMA16816(c, a, b0, b1)                                                     \
    asm volatile("mma.sync.aligned.m16n8k16.row.col.f32.bf16.bf16.f32 "            \
        "{%0,%1,%2,%3}, {%4,%5,%6,%7}, {%8,%9}, {%0,%1,%2,%3};"                    \
        : "+f"((c)[0]), "+f"((c)[1]), "+f"((c)[2]), "+f"((c)[3])                   \
        : "r"((a)[0]), "r"((a)[1]), "r"((a)[2]), "r"((a)[3]), "r"(b0), "r"(b1))

#define CPASYNC16(dst, src)                                                        \
    asm volatile("cp.async.cg.shared.global [%0], [%1], 16;" :: "r"(dst), "l"(src))
#define CPCOMMIT()  asm volatile("cp.async.commit_group;" ::: "memory")
#define CPWAIT0()   asm volatile("cp.async.wait_group 0;" ::: "memory")

__device__ __forceinline__ uint32_t pack_bf2(float a, float b) {
    __nv_bfloat162 t = __floats2bfloat162_rn(a, b);
    return *reinterpret_cast<uint32_t*>(&t);
}

// smem layout (byte offsets from 1024-aligned base)
#define SM_BIAS   0
#define SM_NORM   512
#define SM_NPART  1024
#define SM_SA32(s) (2048 + (s) * 32768)      // f32 A stage, 32KB each
#define SM_AHL(s)  (67584 + (s) * 32768)     // [16KB Ahi | 16KB Alo]
#define SM_BHL(s)  (133120 + (s) * 32768)    // [16KB Bhi | 16KB Blo]
#define STG_STRIDE 132
#define SM_DYN    199680                     // 198656 + align slack

// ---------------- Kernel 0: pre-convert + pre-swizzle W ----------------
__global__ __launch_bounds__(256) void convW_kernel(const float* __restrict__ W)
{
    int idx0 = (blockIdx.x * 256 + threadIdx.x) * 8;
#pragma unroll
    for (int q = 0; q < 8; q++) {
        int idx = idx0 + q;                 // 0..65535
        int row = idx >> 9;                 // 0..127
        int k = idx & 511;
        int kb = k >> 6;
        int k2 = k & 63;
        float w = W[idx];
        __nv_bfloat16 hi = __float2bfloat16_rn(w);
        float hif = __bfloat162float(hi);
        __nv_bfloat16 lo = __float2bfloat16_rn(__fsub_rn(w, hif));
        uint32_t off = kb * 32768u + SWZ128((uint32_t)(row * 128 + k2 * 2));
        *(__nv_bfloat16*)(g_bcvt + off) = hi;
        *(__nv_bfloat16*)(g_bcvt + off + 16384u) = lo;
    }
}

// ---------------- Kernel 1: pipelined split-bf16 mma GEMM + epilogue --------
__global__ __launch_bounds__(256) void gemm_mu_kernel(
    const float* __restrict__ A,
    const float* __restrict__ bias,
    float* __restrict__ out, float kld)
{
    extern __shared__ char dsm[];
    char* p = (char*)(((uintptr_t)dsm + 1023) & ~(uintptr_t)1023);
    uint32_t sb = smem_u32(p);

    int t = threadIdx.x;
    int wid = t >> 5;
    int lane = t & 31;
    int m0 = blockIdx.x * 128;

    int warp_m = wid & 3;
    int warp_n = wid >> 2;
    int m0w = warp_m * 32;
    int n0w = warp_n * 64;

    if (t < 128) *(float*)(p + SM_BIAS + t * 4) = bias[t];

    float c[2][8][4];
#pragma unroll
    for (int mt = 0; mt < 2; mt++)
#pragma unroll
        for (int nt = 0; nt < 8; nt++)
#pragma unroll
            for (int q = 0; q < 4; q++) c[mt][nt][q] = 0.0f;

    int a_row = (lane & 7) + ((lane >> 3) & 1) * 8;
    int a_kb  = (lane >> 4) * 16;
    int b_row = (lane & 7) + (lane >> 4) * 8;
    int b_kb  = ((lane >> 3) & 1) * 16;

    const float* Abase = A + (size_t)m0 * NHID;

    // prologue: issue chunk 0 (A f32 + B bf16 image)
    {
#pragma unroll
        for (int j = 0; j < 8; j++) {
            uint32_t u = (uint32_t)(t + j * 256);       // 16B unit 0..2047
            uint32_t row = u >> 4, kc = (u & 15) * 4;
            CPASYNC16(sb + SM_SA32(0) + u * 16, Abase + row * NHID + kc);
        }
        const unsigned char* srcB = g_bcvt;
#pragma unroll
        for (int j = 0; j < 8; j++) {
            uint32_t o = (uint32_t)(t + j * 256) * 16u;
            CPASYNC16(sb + SM_BHL(0) + o, srcB + o);
        }
        CPCOMMIT();
    }

    for (int kb = 0; kb < 8; kb++) {
        int buf = kb & 1;
        CPWAIT0();
        __syncthreads();    // chunk kb data visible; all mma(kb-1) reads done

        if (kb < 7) {       // issue chunk kb+1 into the other stage
            const float* srcA = Abase + (kb + 1) * 64;
#pragma unroll
            for (int j = 0; j < 8; j++) {
                uint32_t u = (uint32_t)(t + j * 256);
                uint32_t row = u >> 4, kc = (u & 15) * 4;
                CPASYNC16(sb + SM_SA32(buf ^ 1) + u * 16, srcA + row * NHID + kc);
            }
            const unsigned char* srcB = g_bcvt + (size_t)(kb + 1) * 32768u;
#pragma unroll
            for (int j = 0; j < 8; j++) {
                uint32_t o = (uint32_t)(t + j * 256) * 16u;
                CPASYNC16(sb + SM_BHL(buf ^ 1) + o, srcB + o);
            }
            CPCOMMIT();
        }

        // convert A f32 (smem) -> Ahi/Alo bf16 (smem, swizzled)
#pragma unroll
        for (int q = 0; q < 8; q++) {
            int fidx = q * 256 + t;          // lanes contiguous -> conflict-free LDS.128
            int row = fidx >> 4;
            int kq = (fidx & 15) << 2;
            float4 a = *(const float4*)(p + SM_SA32(buf) + fidx * 16);
            uint32_t h01 = pack_bf2(a.x, a.y);
            uint32_t h23 = pack_bf2(a.z, a.w);
            float hx = __uint_as_float(h01 << 16);
            float hy = __uint_as_float(h01 & 0xFFFF0000u);
            float hz = __uint_as_float(h23 << 16);
            float hw = __uint_as_float(h23 & 0xFFFF0000u);
            uint32_t l01 = pack_bf2(__fsub_rn(a.x, hx), __fsub_rn(a.y, hy));
            uint32_t l23 = pack_bf2(__fsub_rn(a.z, hz), __fsub_rn(a.w, hw));
            uint32_t off = SWZ128((uint32_t)(row * 128 + kq * 2));
            *(uint2*)(p + SM_AHL(buf) + off) = make_uint2(h01, h23);
            *(uint2*)(p + SM_AHL(buf) + 16384 + off) = make_uint2(l01, l23);
        }
        __syncthreads();    // conversions visible to ldmatrix

#pragma unroll
        for (int ks = 0; ks < 4; ks++) {
            int kb2 = ks * 32;
            uint32_t ah[2][4], al[2][4];
#pragma unroll
            for (int mt = 0; mt < 2; mt++) {
                uint32_t off = SWZ128((uint32_t)(((m0w + mt * 16 + a_row) << 7) + kb2 + a_kb));
                LDM4(ah[mt], sb + SM_AHL(buf) + off);
                LDM4(al[mt], sb + SM_AHL(buf) + 16384 + off);
            }
#pragma unroll
            for (int half = 0; half < 2; half++) {
                uint32_t bh[2][4], bl[2][4];
#pragma unroll
                for (int g = 0; g < 2; g++) {
                    uint32_t off = SWZ128((uint32_t)(((n0w + half * 32 + g * 16 + b_row) << 7) + kb2 + b_kb));
                    LDM4(bh[g], sb + SM_BHL(buf) + off);
                    LDM4(bl[g], sb + SM_BHL(buf) + 16384 + off);
                }
#pragma unroll
                for (int mt = 0; mt < 2; mt++)
#pragma unroll
                    for (int n4 = 0; n4 < 4; n4++) {
                        int g = n4 >> 1, wch = (n4 & 1) * 2;
                        float* cc = c[mt][half * 4 + n4];
                        MMA16816(cc, ah[mt], bh[g][wch], bh[g][wch + 1]);
                        MMA16816(cc, ah[mt], bl[g][wch], bl[g][wch + 1]);
                        MMA16816(cc, al[mt], bh[g][wch], bh[g][wch + 1]);
                    }
            }
        }
    }
    __syncthreads();

    float* bias_s = (float*)(p + SM_BIAS);
    float* norm_s = (float*)(p + SM_NORM);
    float* npart  = (float*)(p + SM_NPART);
    float* stg    = (float*)(p + SM_SA32(0));

    float rs[4] = {0.0f, 0.0f, 0.0f, 0.0f};
#pragma unroll
    for (int nt = 0; nt < 8; nt++) {
        int col = n0w + nt * 8 + 2 * (lane & 3);
        float b0 = bias_s[col], b1 = bias_s[col + 1];
#pragma unroll
        for (int mt = 0; mt < 2; mt++) {
            c[mt][nt][0] += b0; c[mt][nt][1] += b1;
            c[mt][nt][2] += b0; c[mt][nt][3] += b1;
            rs[mt * 2 + 0] += c[mt][nt][0] * c[mt][nt][0] + c[mt][nt][1] * c[mt][nt][1];
            rs[mt * 2 + 1] += c[mt][nt][2] * c[mt][nt][2] + c[mt][nt][3] * c[mt][nt][3];
            int row = m0w + mt * 16 + (lane >> 2);
            *(float2*)(stg + row * STG_STRIDE + col) = make_float2(c[mt][nt][0], c[mt][nt][1]);
            *(float2*)(stg + (row + 8) * STG_STRIDE + col) = make_float2(c[mt][nt][2], c[mt][nt][3]);
        }
    }
#pragma unroll
    for (int i = 0; i < 4; i++) {
        rs[i] += __shfl_xor_sync(0xffffffffu, rs[i], 1);
        rs[i] += __shfl_xor_sync(0xffffffffu, rs[i], 2);
    }
    if ((lane & 3) == 0) {
        int rbase = m0w + (lane >> 2);
#pragma unroll
        for (int i = 0; i < 4; i++)
            npart[(rbase + i * 8) * 2 + warp_n] = rs[i];
    }
    __syncthreads();

    if (t < 128) {
        float nrm = sqrtf(npart[t * 2] + npart[t * 2 + 1]);
        norm_s[t] = nrm;
        int grow = m0 + t;
        float om = 1.0f - nrm;
        out[OFF_RED + grow] = om * om;
        out[OFF_KLD + grow] = kld;
    }
    __syncthreads();

    float4* muv = (float4*)(out + OFF_MU + (size_t)m0 * NLAT);
#pragma unroll
    for (int j = 0; j < 16; j++) {
        int idx = t * 16 + j;
        int r = idx >> 5;
        int c4 = idx & 31;
        float4 v = *(float4*)(stg + r * STG_STRIDE + c4 * 4);
        float nrm = norm_s[r];
        v.x /= nrm; v.y /= nrm; v.z /= nrm; v.w /= nrm;
        muv[r * 32 + c4] = v;
    }
}

// ---------------- Kernel 2: vMF weight rejection sampler ----------------
__global__ __launch_bounds__(256) void wsample_kernel(Keys2 K, float A1, float A2,
                                                      float Xc, float Cc)
{
    int i = blockIdx.x * 256 + threadIdx.x;
    if (i >= NROWS) return;
    uint32_t ui = (uint32_t)i;
    float w = 0.0f;
#pragma unroll 1
    for (int t = 0; t < TMAX; t++) {
        uint32_t ga0, ga1, gb0, gb1;
        tf2x32(K.ka[t][0], K.ka[t][1], 0u, ui, ga0, ga1);
        tf2x32(K.kb[t][0], K.kb[t][1], 0u, ui, gb0, gb1);
        float lga = log_gamma_one(ga0, ga1);
        float lgb = log_gamma_one(gb0, gb1);
        float mx = fmaxf(lga, lgb);
        float gA = expf(__fsub_rn(lga, mx));
        float gB = expf(__fsub_rn(lgb, mx));
        float z = __fdiv_rn(gA, __fadd_rn(gA, gB));

        float wn = __fdiv_rn(__fsub_rn(1.0f, __fmul_rn(A1, z)),
                             __fsub_rn(1.0f, __fmul_rn(A2, z)));
        float u = u01(rbits(K.ku[t][0], K.ku[t][1], ui));
        float lhs = __fsub_rn(
            __fadd_rn(__fmul_rn(50.0f, wn),
                      __fmul_rn(127.0f, logf(__fsub_rn(1.0f, __fmul_rn(Xc, wn))))),
            Cc);
        if (lhs >= logf(u)) { w = wn; break; }
    }
    g_w[i] = w;
}

// ---------------- Kernel 3: fused normals + orthogonalize + scale -----------
__global__ __launch_bounds__(256) void vecs_kernel(
    const float* __restrict__ mu, float* __restrict__ vecs,
    uint32_t kv0, uint32_t kv1, uint32_t kn0, uint32_t kn1)
{
    int wid = threadIdx.x >> 5;
    int lane = threadIdx.x & 31;
    int b = blockIdx.x * 2 + (wid >> 2);     // 4 warps share one b (mu L2 reuse)
    int n = wid & 3;
    int r = n * NB + b;                       // row index matches JAX layout
    const float* murow = mu + (size_t)b * NLAT;

    float4 m4 = __ldg((const float4*)(murow + lane * 4));

    uint32_t base = (uint32_t)r * 128u + (uint32_t)lane * 4u;
    float4 v4;
    v4.x = jax_normal(rbits(kv0, kv1, base));
    v4.y = jax_normal(rbits(kv0, kv1, base + 1u));
    v4.z = jax_normal(rbits(kv0, kv1, base + 2u));
    v4.w = jax_normal(rbits(kv0, kv1, base + 3u));

    float dot = m4.x * v4.x + m4.y * v4.y + m4.z * v4.z + m4.w * v4.w;
    float msq = m4.x * m4.x + m4.y * m4.y + m4.z * m4.z + m4.w * m4.w;
#pragma unroll
    for (int o = 16; o; o >>= 1) {
        dot += __shfl_xor_sync(0xffffffffu, dot, o);
        msq += __shfl_xor_sync(0xffffffffu, msq, o);
    }
    float mu_n = sqrtf(msq);
    float tproj = dot / mu_n;

    float4 og;
    og.x = v4.x - m4.x * tproj;
    og.y = v4.y - m4.y * tproj;
    og.z = v4.z - m4.z * tproj;
    og.w = v4.w - m4.w * tproj;
    float osq = og.x * og.x + og.y * og.y + og.z * og.z + og.w * og.w;
#pragma unroll
    for (int o = 16; o; o >>= 1) osq += __shfl_xor_sync(0xffffffffu, osq, o);
    float onorm = sqrtf(osq);

    float w = 0.0f, nn = 0.0f;
    if (lane == 0) {
        w = g_w[r];
        nn = 1.0f + u01(rbits(kn0, kn1, (uint32_t)r));
    }
    w = __shfl_sync(0xffffffffu, w, 0);
    nn = __shfl_sync(0xffffffffu, nn, 0);
    float s = sqrtf(1.0f - w * w);

    float4 ov;
    ov.x = (og.x / onorm * s + m4.x * w) * nn;
    ov.y = (og.y / onorm * s + m4.y * w) * nn;
    ov.z = (og.z / onorm * s + m4.z * w) * nn;
    ov.w = (og.w / onorm * s + m4.w * w) * nn;
    *(float4*)(vecs + (size_t)r * NLAT + lane * 4) = ov;
}

// ---------------- Host ----------------
static double host_log_iv(double nu, double k) {
    const int M = 300;
    double logt[M];
    double mx = -1e300;
    for (int m = 0; m < M; m++) {
        double tv = (2.0 * m + nu) * log(k / 2.0) - lgamma(m + 1.0) - lgamma(m + nu + 1.0);
        logt[m] = tv;
        if (tv > mx) mx = tv;
    }
    double s = 0.0;
    for (int m = 0; m < M; m++) s += exp(logt[m] - mx);
    return mx + log(s);
}

extern "C" void kernel_launch(void* const* d_in, const int* in_sizes, int n_in,
                              void* d_out, int out_size)
{
    const float* lat = (const float*)d_in[0];
    const float* Wm  = (const float*)d_in[1];
    const float* bm  = (const float*)d_in[2];
    float* out = (float*)d_out;

    const double dd = 127.0, kap = 50.0;
    double b = dd / (sqrt(4.0 * kap * kap + dd * dd) + 2.0 * kap);
    double x = (1.0 - b) / (1.0 + b);
    double c = kap * x + dd * log(1.0 - x * x);
    float A1 = (float)(1.0 + b), A2 = (float)(1.0 - b);
    float Xc = (float)x, Cc = (float)c;

    const double D = 128.0;
    double liv0 = host_log_iv(D / 2.0, kap);
    double liv1 = host_log_iv(D / 2.0 + 1.0, kap);
    double ratio = exp(liv1 - liv0);
    double a_ = D / (2.0 * kap);
    double vmf = kap * (ratio + a_ - a_) + D * log(kap) / 2.0 - liv0
               - lgamma(D / 2.0 + 1.0) - D * log(2.0) / 2.0;
    float kld = (float)(vmf + log(2.0 / 1.0));

    uint32_t kw0, kw1, kv0, kv1, kn0, kn1;
    tf2x32(0u, 1u, 0u, 0u, kw0, kw1);
    tf2x32(0u, 1u, 0u, 1u, kv0, kv1);
    tf2x32(0u, 1u, 0u, 2u, kn0, kn1);

    Keys2 K;
    uint32_t c0 = kw0, c1 = kw1;
    for (int t = 0; t < TMAX; t++) {
        uint32_t nk0, nk1, kz0, kz1, ku0, ku1;
        tf2x32(c0, c1, 0u, 0u, nk0, nk1);
        tf2x32(c0, c1, 0u, 1u, kz0, kz1);
        tf2x32(c0, c1, 0u, 2u, ku0, ku1);
        tf2x32(kz0, kz1, 0u, 0u, K.ka[t][0], K.ka[t][1]);
        tf2x32(kz0, kz1, 0u, 1u, K.kb[t][0], K.kb[t][1]);
        K.ku[t][0] = ku0; K.ku[t][1] = ku1;
        c0 = nk0; c1 = nk1;
    }

    static cudaStream_t s1 = nullptr;
    static cudaEvent_t eFork = nullptr, eSide = nullptr;
    if (!s1) {
        cudaStreamCreateWithFlags(&s1, cudaStreamNonBlocking);
        cudaEventCreateWithFlags(&eFork, cudaEventDisableTiming);
        cudaEventCreateWithFlags(&eSide, cudaEventDisableTiming);
        cudaFuncSetAttribute(gemm_mu_kernel,
                             cudaFuncAttributeMaxDynamicSharedMemorySize, SM_DYN);
    }

    // fork: wsample on side stream, GEMM path on main stream
    cudaEventRecord(eFork, 0);
    cudaStreamWaitEvent(s1, eFork, 0);
    wsample_kernel<<<NROWS / 256, 256, 0, s1>>>(K, A1, A2, Xc, Cc);
    cudaEventRecord(eSide, s1);

    convW_kernel<<<32, 256>>>(Wm);
    gemm_mu_kernel<<<NB / 128, 256, SM_DYN>>>(lat, bm, out, kld);

    cudaStreamWaitEvent(0, eSide, 0);
    vecs_kernel<<<NB / 2, 256>>>(out + OFF_MU, out + OFF_VECS, kv0, kv1, kn0, kn1);
}

// round 15
// speedup vs baseline: 1.4023x; 1.0059x over previous
#include <cuda_runtime.h>
#include <cuda_bf16.h>
#include <cstdint>
#include <math.h>

#define NB    65536
#define NHID  512
#define NLAT  128
#define NS    4
#define NROWS (NS*NB)          // 262144
#define TMAX  32
#define NQ    4                // batch quarters for gemm->vecs pipelining

#define OFF_VECS 0
#define OFF_KLD  (33554432)
#define OFF_MU   (OFF_KLD + NB)
#define OFF_RED  (OFF_MU + NB*NLAT)

// scratch (no cudaMalloc allowed)
__device__ float g_w[NROWS];
// pre-converted, pre-swizzled W images: per chunk kb (64 K): [16KB hi | 16KB lo]
__device__ __align__(128) unsigned char g_bcvt[8 * 32768];

struct Keys2 {
    uint32_t ka[TMAX][2];
    uint32_t kb[TMAX][2];
    uint32_t ku[TMAX][2];
};

// ---------------- Threefry-2x32 (JAX exact) ----------------
__host__ __device__ __forceinline__ void tf2x32(uint32_t k0, uint32_t k1,
                                                uint32_t x0, uint32_t x1,
                                                uint32_t& o0, uint32_t& o1) {
    uint32_t ks2 = k0 ^ k1 ^ 0x1BD11BDAu;
    x0 += k0; x1 += k1;
#define TFR(r) { x0 += x1; x1 = (x1 << (r)) | (x1 >> (32 - (r))); x1 ^= x0; }
    TFR(13) TFR(15) TFR(26) TFR(6)   x0 += k1;  x1 += ks2 + 1u;
    TFR(17) TFR(29) TFR(16) TFR(24)  x0 += ks2; x1 += k0 + 2u;
    TFR(13) TFR(15) TFR(26) TFR(6)   x0 += k0;  x1 += k1 + 3u;
    TFR(17) TFR(29) TFR(16) TFR(24)  x0 += k1;  x1 += ks2 + 4u;
    TFR(13) TFR(15) TFR(26) TFR(6)   x0 += ks2; x1 += k0 + 5u;
#undef TFR
    o0 = x0; o1 = x1;
}

__device__ __forceinline__ uint32_t rbits(uint32_t k0, uint32_t k1, uint32_t idx) {
    uint32_t o0, o1;
    tf2x32(k0, k1, 0u, idx, o0, o1);
    return o0 ^ o1;
}

__device__ __forceinline__ float u01(uint32_t bits) {
    return __uint_as_float((bits >> 9) | 0x3f800000u) - 1.0f;
}

// XLA ErfInv32 — exact constants & op order
__device__ __forceinline__ float erfinv_xla(float x) {
    float w = -log1pf(-__fmul_rn(x, x));
    float p;
    if (w < 5.0f) {
        w = __fsub_rn(w, 2.5f);
        p = 2.81022636e-08f;
        p = __fadd_rn(3.43273939e-07f,  __fmul_rn(p, w));
        p = __fadd_rn(-3.5233877e-06f,  __fmul_rn(p, w));
        p = __fadd_rn(-4.39150654e-06f, __fmul_rn(p, w));
        p = __fadd_rn(0.00021858087f,   __fmul_rn(p, w));
        p = __fadd_rn(-0.00125372503f,  __fmul_rn(p, w));
        p = __fadd_rn(-0.00417768164f,  __fmul_rn(p, w));
        p = __fadd_rn(0.246640727f,     __fmul_rn(p, w));
        p = __fadd_rn(1.50140941f,      __fmul_rn(p, w));
    } else {
        w = __fsub_rn(sqrtf(w), 3.0f);
        p = -0.000200214257f;
        p = __fadd_rn(0.000100950558f,  __fmul_rn(p, w));
        p = __fadd_rn(0.00134934322f,   __fmul_rn(p, w));
        p = __fadd_rn(-0.00367342844f,  __fmul_rn(p, w));
        p = __fadd_rn(0.00573950773f,   __fmul_rn(p, w));
        p = __fadd_rn(-0.0076224613f,   __fmul_rn(p, w));
        p = __fadd_rn(0.00943887047f,   __fmul_rn(p, w));
        p = __fadd_rn(1.00167406f,      __fmul_rn(p, w));
        p = __fadd_rn(2.83297682f,      __fmul_rn(p, w));
    }
    return __fmul_rn(p, x);
}

__device__ __forceinline__ float jax_normal(uint32_t bits) {
    const float lo = -0.99999994f;
    float f = u01(bits);
    float u = __fadd_rn(__fmul_rn(f, 2.0f), lo);
    u = fmaxf(lo, u);
    return __fmul_rn(1.41421356237f, erfinv_xla(u));
}

// jax _gamma_one(key, alpha=63.5, log_space=True) — exact chain
__device__ __forceinline__ float log_gamma_one(uint32_t gk0, uint32_t gk1) {
    const float one_third = 0.33333334f;
    float dg = __fsub_rn(63.5f, one_third);
    float cg = __fdiv_rn(one_third, sqrtf(dg));

    uint32_t key0, key1;
    tf2x32(gk0, gk1, 0u, 0u, key0, key1);

    while (true) {
        uint32_t nk0, nk1, xk0, xk1, Uk0, Uk1;
        tf2x32(key0, key1, 0u, 0u, nk0, nk1);
        tf2x32(key0, key1, 0u, 1u, xk0, xk1);
        tf2x32(key0, key1, 0u, 2u, Uk0, Uk1);
        key0 = nk0; key1 = nk1;

        float x, v;
        uint32_t cx0 = xk0, cx1 = xk1;
        while (true) {
            uint32_t s0, s1;
            tf2x32(cx0, cx1, 0u, 1u, s0, s1);
            x = jax_normal(rbits(s0, s1, 0u));
            v = __fadd_rn(1.0f, __fmul_rn(x, cg));
            if (v > 0.0f) break;
            uint32_t n0, n1;
            tf2x32(cx0, cx1, 0u, 0u, n0, n1);
            cx0 = n0; cx1 = n1;
        }

        float X = __fmul_rn(x, x);
        float V = __fmul_rn(__fmul_rn(v, v), v);
        float U = u01(rbits(Uk0, Uk1, 0u));

        float sq = __fsub_rn(1.0f, __fmul_rn(0.0331f, __fmul_rn(X, X)));
        bool cont;
        if (U < sq) {
            cont = false;
        } else {
            float th = __fadd_rn(__fmul_rn(X, 0.5f),
                                 __fmul_rn(dg, __fadd_rn(__fsub_rn(1.0f, V), logf(V))));
            cont = (logf(U) >= th);
        }
        if (!cont) return __fadd_rn(logf(V), logf(dg));
    }
}

// ================= mma.sync helpers =================
__device__ __forceinline__ uint32_t smem_u32(const void* p) {
    uint32_t a;
    asm("{ .reg .u64 t; cvta.to.shared.u64 t, %1; cvt.u32.u64 %0, t; }"
        : "=r"(a) : "l"(p));
    return a;
}
#define SWZ128(o) ((o) ^ (((o) >> 3) & 0x70))

#define LDM4(r, addr)                                                              \
    asm volatile("ldmatrix.sync.aligned.m8n8.x4.shared.b16 {%0,%1,%2,%3}, [%4];"   \
        : "=r"((r)[0]), "=r"((r)[1]), "=r"((r)[2]), "=r"((r)[3]) : "r"(addr))

#define MMA16816(c, a, b0, b1)                                                     \
    asm volatile("mma.sync.aligned.m16n8k16.row.col.f32.bf16.bf16.f32 "            \
        "{%0,%1,%2,%3}, {%4,%5,%6,%7}, {%8,%9}, {%0,%1,%2,%3};"                    \
        : "+f"((c)[0]), "+f"((c)[1]), "+f"((c)[2]), "+f"((c)[3])                   \
        : "r"((a)[0]), "r"((a)[1]), "r"((a)[2]), "r"((a)[3]), "r"(b0), "r"(b1))

#define CPASYNC16(dst, src)                                                        \
    asm volatile("cp.async.cg.shared.global [%0], [%1], 16;" :: "r"(dst), "l"(src))
#define CPCOMMIT()  asm volatile("cp.async.commit_group;" ::: "memory")
#define CPWAIT0()   asm volatile("cp.async.wait_group 0;" ::: "memory")

__device__ __forceinline__ uint32_t pack_bf2(float a, float b) {
    __nv_bfloat162 t = __floats2bfloat162_rn(a, b);
    return *reinterpret_cast<uint32_t*>(&t);
}

// smem layout (byte offsets from 1024-aligned base)
#define SM_BIAS   0
#define SM_NORM   512
#define SM_NPART  1024
#define SM_SA32(s) (2048 + (s) * 32768)      // f32 A stage, 32KB each
#define SM_AHL(s)  (67584 + (s) * 32768)     // [16KB Ahi | 16KB Alo]
#define SM_BHL(s)  (133120 + (s) * 32768)    // [16KB Bhi | 16KB Blo]
#define STG_STRIDE 132
#define SM_DYN    199680

// ---------------- Kernel 0: pre-convert + pre-swizzle W ----------------
__global__ __launch_bounds__(256) void convW_kernel(const float* __restrict__ W)
{
    int idx0 = (blockIdx.x * 256 + threadIdx.x) * 8;
#pragma unroll
    for (int q = 0; q < 8; q++) {
        int idx = idx0 + q;                 // 0..65535
        int row = idx >> 9;                 // 0..127
        int k = idx & 511;
        int kb = k >> 6;
        int k2 = k & 63;
        float w = W[idx];
        __nv_bfloat16 hi = __float2bfloat16_rn(w);
        float hif = __bfloat162float(hi);
        __nv_bfloat16 lo = __float2bfloat16_rn(__fsub_rn(w, hif));
        uint32_t off = kb * 32768u + SWZ128((uint32_t)(row * 128 + k2 * 2));
        *(__nv_bfloat16*)(g_bcvt + off) = hi;
        *(__nv_bfloat16*)(g_bcvt + off + 16384u) = lo;
    }
}

// ---------------- Kernel 1: pipelined split-bf16 mma GEMM + epilogue --------
__global__ __launch_bounds__(256) void gemm_mu_kernel(
    const float* __restrict__ A,
    const float* __restrict__ bias,
    float* __restrict__ out, float kld, int cta0)
{
    extern __shared__ char dsm[];
    char* p = (char*)(((uintptr_t)dsm + 1023) & ~(uintptr_t)1023);
    uint32_t sb = smem_u32(p);

    int t = threadIdx.x;
    int wid = t >> 5;
    int lane = t & 31;
    int m0 = (cta0 + blockIdx.x) * 128;

    int warp_m = wid & 3;
    int warp_n = wid >> 2;
    int m0w = warp_m * 32;
    int n0w = warp_n * 64;

    if (t < 128) *(float*)(p + SM_BIAS + t * 4) = bias[t];

    float c[2][8][4];
#pragma unroll
    for (int mt = 0; mt < 2; mt++)
#pragma unroll
        for (int nt = 0; nt < 8; nt++)
#pragma unroll
            for (int q = 0; q < 4; q++) c[mt][nt][q] = 0.0f;

    int a_row = (lane & 7) + ((lane >> 3) & 1) * 8;
    int a_kb  = (lane >> 4) * 16;
    int b_row = (lane & 7) + (lane >> 4) * 8;
    int b_kb  = ((lane >> 3) & 1) * 16;

    const float* Abase = A + (size_t)m0 * NHID;

    // prologue: issue chunk 0 (A f32 + B bf16 image)
    {
#pragma unroll
        for (int j = 0; j < 8; j++) {
            uint32_t u = (uint32_t)(t + j * 256);
            uint32_t row = u >> 4, kc = (u & 15) * 4;
            CPASYNC16(sb + SM_SA32(0) + u * 16, Abase + row * NHID + kc);
        }
        const unsigned char* srcB = g_bcvt;
#pragma unroll
        for (int j = 0; j < 8; j++) {
            uint32_t o = (uint32_t)(t + j * 256) * 16u;
            CPASYNC16(sb + SM_BHL(0) + o, srcB + o);
        }
        CPCOMMIT();
    }

    for (int kb = 0; kb < 8; kb++) {
        int buf = kb & 1;
        CPWAIT0();
        __syncthreads();

        if (kb < 7) {
            const float* srcA = Abase + (kb + 1) * 64;
#pragma unroll
            for (int j = 0; j < 8; j++) {
                uint32_t u = (uint32_t)(t + j * 256);
                uint32_t row = u >> 4, kc = (u & 15) * 4;
                CPASYNC16(sb + SM_SA32(buf ^ 1) + u * 16, srcA + row * NHID + kc);
            }
            const unsigned char* srcB = g_bcvt + (size_t)(kb + 1) * 32768u;
#pragma unroll
            for (int j = 0; j < 8; j++) {
                uint32_t o = (uint32_t)(t + j * 256) * 16u;
                CPASYNC16(sb + SM_BHL(buf ^ 1) + o, srcB + o);
            }
            CPCOMMIT();
        }

#pragma unroll
        for (int q = 0; q < 8; q++) {
            int fidx = q * 256 + t;
            int row = fidx >> 4;
            int kq = (fidx & 15) << 2;
            float4 a = *(const float4*)(p + SM_SA32(buf) + fidx * 16);
            uint32_t h01 = pack_bf2(a.x, a.y);
            uint32_t h23 = pack_bf2(a.z, a.w);
            float hx = __uint_as_float(h01 << 16);
            float hy = __uint_as_float(h01 & 0xFFFF0000u);
            float hz = __uint_as_float(h23 << 16);
            float hw = __uint_as_float(h23 & 0xFFFF0000u);
            uint32_t l01 = pack_bf2(__fsub_rn(a.x, hx), __fsub_rn(a.y, hy));
            uint32_t l23 = pack_bf2(__fsub_rn(a.z, hz), __fsub_rn(a.w, hw));
            uint32_t off = SWZ128((uint32_t)(row * 128 + kq * 2));
            *(uint2*)(p + SM_AHL(buf) + off) = make_uint2(h01, h23);
            *(uint2*)(p + SM_AHL(buf) + 16384 + off) = make_uint2(l01, l23);
        }
        __syncthreads();

#pragma unroll
        for (int ks = 0; ks < 4; ks++) {
            int kb2 = ks * 32;
            uint32_t ah[2][4], al[2][4];
#pragma unroll
            for (int mt = 0; mt < 2; mt++) {
                uint32_t off = SWZ128((uint32_t)(((m0w + mt * 16 + a_row) << 7) + kb2 + a_kb));
                LDM4(ah[mt], sb + SM_AHL(buf) + off);
                LDM4(al[mt], sb + SM_AHL(buf) + 16384 + off);
            }
#pragma unroll
            for (int half = 0; half < 2; half++) {
                uint32_t bh[2][4], bl[2][4];
#pragma unroll
                for (int g = 0; g < 2; g++) {
                    uint32_t off = SWZ128((uint32_t)(((n0w + half * 32 + g * 16 + b_row) << 7) + kb2 + b_kb));
                    LDM4(bh[g], sb + SM_BHL(buf) + off);
                    LDM4(bl[g], sb + SM_BHL(buf) + 16384 + off);
                }
#pragma unroll
                for (int mt = 0; mt < 2; mt++)
#pragma unroll
                    for (int n4 = 0; n4 < 4; n4++) {
                        int g = n4 >> 1, wch = (n4 & 1) * 2;
                        float* cc = c[mt][half * 4 + n4];
                        MMA16816(cc, ah[mt], bh[g][wch], bh[g][wch + 1]);
                        MMA16816(cc, ah[mt], bl[g][wch], bl[g][wch + 1]);
                        MMA16816(cc, al[mt], bh[g][wch], bh[g][wch + 1]);
                    }
            }
        }
    }
    __syncthreads();

    float* bias_s = (float*)(p + SM_BIAS);
    float* norm_s = (float*)(p + SM_NORM);
    float* npart  = (float*)(p + SM_NPART);
    float* stg    = (float*)(p + SM_SA32(0));

    float rs[4] = {0.0f, 0.0f, 0.0f, 0.0f};
#pragma unroll
    for (int nt = 0; nt < 8; nt++) {
        int col = n0w + nt * 8 + 2 * (lane & 3);
        float b0 = bias_s[col], b1 = bias_s[col + 1];
#pragma unroll
        for (int mt = 0; mt < 2; mt++) {
            c[mt][nt][0] += b0; c[mt][nt][1] += b1;
            c[mt][nt][2] += b0; c[mt][nt][3] += b1;
            rs[mt * 2 + 0] += c[mt][nt][0] * c[mt][nt][0] + c[mt][nt][1] * c[mt][nt][1];
            rs[mt * 2 + 1] += c[mt][nt][2] * c[mt][nt][2] + c[mt][nt][3] * c[mt][nt][3];
            int row = m0w + mt * 16 + (lane >> 2);
            *(float2*)(stg + row * STG_STRIDE + col) = make_float2(c[mt][nt][0], c[mt][nt][1]);
            *(float2*)(stg + (row + 8) * STG_STRIDE + col) = make_float2(c[mt][nt][2], c[mt][nt][3]);
        }
    }
#pragma unroll
    for (int i = 0; i < 4; i++) {
        rs[i] += __shfl_xor_sync(0xffffffffu, rs[i], 1);
        rs[i] += __shfl_xor_sync(0xffffffffu, rs[i], 2);
    }
    if ((lane & 3) == 0) {
        int rbase = m0w + (lane >> 2);
#pragma unroll
        for (int i = 0; i < 4; i++)
            npart[(rbase + i * 8) * 2 + warp_n] = rs[i];
    }
    __syncthreads();

    if (t < 128) {
        float nrm = sqrtf(npart[t * 2] + npart[t * 2 + 1]);
        norm_s[t] = nrm;
        int grow = m0 + t;
        float om = 1.0f - nrm;
        out[OFF_RED + grow] = om * om;
        out[OFF_KLD + grow] = kld;
    }
    __syncthreads();

    float4* muv = (float4*)(out + OFF_MU + (size_t)m0 * NLAT);
#pragma unroll
    for (int j = 0; j < 16; j++) {
        int idx = t * 16 + j;
        int r = idx >> 5;
        int c4 = idx & 31;
        float4 v = *(float4*)(stg + r * STG_STRIDE + c4 * 4);
        float nrm = norm_s[r];
        v.x /= nrm; v.y /= nrm; v.z /= nrm; v.w /= nrm;
        muv[r * 32 + c4] = v;
    }
}

// ---------------- Kernel 2: vMF weight rejection sampler ----------------
__global__ __launch_bounds__(256) void wsample_kernel(Keys2 K, float A1, float A2,
                                                      float Xc, float Cc)
{
    int i = blockIdx.x * 256 + threadIdx.x;
    if (i >= NROWS) return;
    uint32_t ui = (uint32_t)i;
    float w = 0.0f;
#pragma unroll 1
    for (int t = 0; t < TMAX; t++) {
        uint32_t ga0, ga1, gb0, gb1;
        tf2x32(K.ka[t][0], K.ka[t][1], 0u, ui, ga0, ga1);
        tf2x32(K.kb[t][0], K.kb[t][1], 0u, ui, gb0, gb1);
        float lga = log_gamma_one(ga0, ga1);
        float lgb = log_gamma_one(gb0, gb1);
        float mx = fmaxf(lga, lgb);
        float gA = expf(__fsub_rn(lga, mx));
        float gB = expf(__fsub_rn(lgb, mx));
        float z = __fdiv_rn(gA, __fadd_rn(gA, gB));

        float wn = __fdiv_rn(__fsub_rn(1.0f, __fmul_rn(A1, z)),
                             __fsub_rn(1.0f, __fmul_rn(A2, z)));
        float u = u01(rbits(K.ku[t][0], K.ku[t][1], ui));
        float lhs = __fsub_rn(
            __fadd_rn(__fmul_rn(50.0f, wn),
                      __fmul_rn(127.0f, logf(__fsub_rn(1.0f, __fmul_rn(Xc, wn))))),
            Cc);
        if (lhs >= logf(u)) { w = wn; break; }
    }
    g_w[i] = w;
}

// ---------------- Kernel 3: fused normals + orthogonalize + scale -----------
__global__ __launch_bounds__(256) void vecs_kernel(
    const float* __restrict__ mu, float* __restrict__ vecs,
    uint32_t kv0, uint32_t kv1, uint32_t kn0, uint32_t kn1, int b0)
{
    int wid = threadIdx.x >> 5;
    int lane = threadIdx.x & 31;
    int b = b0 + blockIdx.x * 2 + (wid >> 2);  // 4 warps share one b (mu L2 reuse)
    int n = wid & 3;
    int r = n * NB + b;                         // row index matches JAX layout
    const float* murow = mu + (size_t)b * NLAT;

    float4 m4 = __ldg((const float4*)(murow + lane * 4));

    uint32_t base = (uint32_t)r * 128u + (uint32_t)lane * 4u;
    float4 v4;
    v4.x = jax_normal(rbits(kv0, kv1, base));
    v4.y = jax_normal(rbits(kv0, kv1, base + 1u));
    v4.z = jax_normal(rbits(kv0, kv1, base + 2u));
    v4.w = jax_normal(rbits(kv0, kv1, base + 3u));

    float dot = m4.x * v4.x + m4.y * v4.y + m4.z * v4.z + m4.w * v4.w;
    float msq = m4.x * m4.x + m4.y * m4.y + m4.z * m4.z + m4.w * m4.w;
#pragma unroll
    for (int o = 16; o; o >>= 1) {
        dot += __shfl_xor_sync(0xffffffffu, dot, o);
        msq += __shfl_xor_sync(0xffffffffu, msq, o);
    }
    float mu_n = sqrtf(msq);
    float tproj = dot / mu_n;

    float4 og;
    og.x = v4.x - m4.x * tproj;
    og.y = v4.y - m4.y * tproj;
    og.z = v4.z - m4.z * tproj;
    og.w = v4.w - m4.w * tproj;
    float osq = og.x * og.x + og.y * og.y + og.z * og.z + og.w * og.w;
#pragma unroll
    for (int o = 16; o; o >>= 1) osq += __shfl_xor_sync(0xffffffffu, osq, o);
    float onorm = sqrtf(osq);

    float w = 0.0f, nn = 0.0f;
    if (lane == 0) {
        w = g_w[r];
        nn = 1.0f + u01(rbits(kn0, kn1, (uint32_t)r));
    }
    w = __shfl_sync(0xffffffffu, w, 0);
    nn = __shfl_sync(0xffffffffu, nn, 0);
    float s = sqrtf(1.0f - w * w);

    float4 ov;
    ov.x = (og.x / onorm * s + m4.x * w) * nn;
    ov.y = (og.y / onorm * s + m4.y * w) * nn;
    ov.z = (og.z / onorm * s + m4.z * w) * nn;
    ov.w = (og.w / onorm * s + m4.w * w) * nn;
    *(float4*)(vecs + (size_t)r * NLAT + lane * 4) = ov;
}

// ---------------- Host ----------------
static double host_log_iv(double nu, double k) {
    const int M = 300;
    double logt[M];
    double mx = -1e300;
    for (int m = 0; m < M; m++) {
        double tv = (2.0 * m + nu) * log(k / 2.0) - lgamma(m + 1.0) - lgamma(m + nu + 1.0);
        logt[m] = tv;
        if (tv > mx) mx = tv;
    }
    double s = 0.0;
    for (int m = 0; m < M; m++) s += exp(logt[m] - mx);
    return mx + log(s);
}

extern "C" void kernel_launch(void* const* d_in, const int* in_sizes, int n_in,
                              void* d_out, int out_size)
{
    const float* lat = (const float*)d_in[0];
    const float* Wm  = (const float*)d_in[1];
    const float* bm  = (const float*)d_in[2];
    float* out = (float*)d_out;

    const double dd = 127.0, kap = 50.0;
    double b = dd / (sqrt(4.0 * kap * kap + dd * dd) + 2.0 * kap);
    double x = (1.0 - b) / (1.0 + b);
    double c = kap * x + dd * log(1.0 - x * x);
    float A1 = (float)(1.0 + b), A2 = (float)(1.0 - b);
    float Xc = (float)x, Cc = (float)c;

    const double D = 128.0;
    double liv0 = host_log_iv(D / 2.0, kap);
    double liv1 = host_log_iv(D / 2.0 + 1.0, kap);
    double ratio = exp(liv1 - liv0);
    double a_ = D / (2.0 * kap);
    double vmf = kap * (ratio + a_ - a_) + D * log(kap) / 2.0 - liv0
               - lgamma(D / 2.0 + 1.0) - D * log(2.0) / 2.0;
    float kld = (float)(vmf + log(2.0 / 1.0));

    uint32_t kw0, kw1, kv0, kv1, kn0, kn1;
    tf2x32(0u, 1u, 0u, 0u, kw0, kw1);
    tf2x32(0u, 1u, 0u, 1u, kv0, kv1);
    tf2x32(0u, 1u, 0u, 2u, kn0, kn1);

    Keys2 K;
    uint32_t c0 = kw0, c1 = kw1;
    for (int t = 0; t < TMAX; t++) {
        uint32_t nk0, nk1, kz0, kz1, ku0, ku1;
        tf2x32(c0, c1, 0u, 0u, nk0, nk1);
        tf2x32(c0, c1, 0u, 1u, kz0, kz1);
        tf2x32(c0, c1, 0u, 2u, ku0, ku1);
        tf2x32(kz0, kz1, 0u, 0u, K.ka[t][0], K.ka[t][1]);
        tf2x32(kz0, kz1, 0u, 1u, K.kb[t][0], K.kb[t][1]);
        K.ku[t][0] = ku0; K.ku[t][1] = ku1;
        c0 = nk0; c1 = nk1;
    }

    static cudaStream_t s1 = nullptr;
    static cudaEvent_t eFork = nullptr, eQ[NQ] = {}, eSide = nullptr;
    if (!s1) {
        cudaStreamCreateWithFlags(&s1, cudaStreamNonBlocking);
        cudaEventCreateWithFlags(&eFork, cudaEventDisableTiming);
        for (int i = 0; i < NQ; i++)
            cudaEventCreateWithFlags(&eQ[i], cudaEventDisableTiming);
        cudaEventCreateWithFlags(&eSide, cudaEventDisableTiming);
        cudaFuncSetAttribute(gemm_mu_kernel,
                             cudaFuncAttributeMaxDynamicSharedMemorySize, SM_DYN);
    }

    const int CTAS = NB / 128;           // 512 gemm CTAs total
    const int CQ = CTAS / NQ;            // CTAs per quarter
    const int BQ = NB / NQ;              // batch rows per quarter

    // fork: wsample on side stream (vecs needs g_w)
    cudaEventRecord(eFork, 0);
    cudaStreamWaitEvent(s1, eFork, 0);
    wsample_kernel<<<NROWS / 256, 256, 0, s1>>>(K, A1, A2, Xc, Cc);

    // main stream: convW, then gemm by quarters; event after each quarter
    convW_kernel<<<32, 256>>>(Wm);
    for (int q = 0; q < NQ; q++) {
        gemm_mu_kernel<<<CQ, 256, SM_DYN>>>(lat, bm, out, kld, q * CQ);
        cudaEventRecord(eQ[q], 0);
    }

    // side stream: vecs quarter q as soon as its mu rows exist (+ g_w ready)
    for (int q = 0; q < NQ; q++) {
        cudaStreamWaitEvent(s1, eQ[q], 0);
        vecs_kernel<<<BQ / 2, 256, 0, s1>>>(out + OFF_MU, out + OFF_VECS,
                                            kv0, kv1, kn0, kn1, q * BQ);
    }
    cudaEventRecord(eSide, s1);
    cudaStreamWaitEvent(0, eSide, 0);
}

// round 16
// speedup vs baseline: 1.6183x; 1.1540x over previous
#include <cuda_runtime.h>
#include <cuda_bf16.h>
#include <cstdint>
#include <math.h>

#define NB    65536
#define NHID  512
#define NLAT  128
#define NS    4
#define NROWS (NS*NB)          // 262144
#define TMAX  32

#define OFF_VECS 0
#define OFF_KLD  (33554432)
#define OFF_MU   (OFF_KLD + NB)
#define OFF_RED  (OFF_MU + NB*NLAT)

// scratch (no cudaMalloc allowed)
__device__ float g_w[NROWS];
// pre-converted, pre-swizzled W images: per chunk kb (64 K): [16KB hi | 16KB lo]
__device__ __align__(128) unsigned char g_bcvt[8 * 32768];

struct Keys2 {
    uint32_t ka[TMAX][2];
    uint32_t kb[TMAX][2];
    uint32_t ku[TMAX][2];
};

// ---------------- Threefry-2x32 (JAX exact) ----------------
__host__ __device__ __forceinline__ void tf2x32(uint32_t k0, uint32_t k1,
                                                uint32_t x0, uint32_t x1,
                                                uint32_t& o0, uint32_t& o1) {
    uint32_t ks2 = k0 ^ k1 ^ 0x1BD11BDAu;
    x0 += k0; x1 += k1;
#define TFR(r) { x0 += x1; x1 = (x1 << (r)) | (x1 >> (32 - (r))); x1 ^= x0; }
    TFR(13) TFR(15) TFR(26) TFR(6)   x0 += k1;  x1 += ks2 + 1u;
    TFR(17) TFR(29) TFR(16) TFR(24)  x0 += ks2; x1 += k0 + 2u;
    TFR(13) TFR(15) TFR(26) TFR(6)   x0 += k0;  x1 += k1 + 3u;
    TFR(17) TFR(29) TFR(16) TFR(24)  x0 += k1;  x1 += ks2 + 4u;
    TFR(13) TFR(15) TFR(26) TFR(6)   x0 += ks2; x1 += k0 + 5u;
#undef TFR
    o0 = x0; o1 = x1;
}

__device__ __forceinline__ uint32_t rbits(uint32_t k0, uint32_t k1, uint32_t idx) {
    uint32_t o0, o1;
    tf2x32(k0, k1, 0u, idx, o0, o1);
    return o0 ^ o1;
}

__device__ __forceinline__ float u01(uint32_t bits) {
    return __uint_as_float((bits >> 9) | 0x3f800000u) - 1.0f;
}

// XLA ErfInv32 — exact constants & op order (used on accept/reject paths only)
__device__ __forceinline__ float erfinv_xla(float x) {
    float w = -log1pf(-__fmul_rn(x, x));
    float p;
    if (w < 5.0f) {
        w = __fsub_rn(w, 2.5f);
        p = 2.81022636e-08f;
        p = __fadd_rn(3.43273939e-07f,  __fmul_rn(p, w));
        p = __fadd_rn(-3.5233877e-06f,  __fmul_rn(p, w));
        p = __fadd_rn(-4.39150654e-06f, __fmul_rn(p, w));
        p = __fadd_rn(0.00021858087f,   __fmul_rn(p, w));
        p = __fadd_rn(-0.00125372503f,  __fmul_rn(p, w));
        p = __fadd_rn(-0.00417768164f,  __fmul_rn(p, w));
        p = __fadd_rn(0.246640727f,     __fmul_rn(p, w));
        p = __fadd_rn(1.50140941f,      __fmul_rn(p, w));
    } else {
        w = __fsub_rn(sqrtf(w), 3.0f);
        p = -0.000200214257f;
        p = __fadd_rn(0.000100950558f,  __fmul_rn(p, w));
        p = __fadd_rn(0.00134934322f,   __fmul_rn(p, w));
        p = __fadd_rn(-0.00367342844f,  __fmul_rn(p, w));
        p = __fadd_rn(0.00573950773f,   __fmul_rn(p, w));
        p = __fadd_rn(-0.0076224613f,   __fmul_rn(p, w));
        p = __fadd_rn(0.00943887047f,   __fmul_rn(p, w));
        p = __fadd_rn(1.00167406f,      __fmul_rn(p, w));
        p = __fadd_rn(2.83297682f,      __fmul_rn(p, w));
    }
    return __fmul_rn(p, x);
}

__device__ __forceinline__ float jax_normal(uint32_t bits) {
    const float lo = -0.99999994f;
    float f = u01(bits);
    float u = __fadd_rn(__fmul_rn(f, 2.0f), lo);
    u = fmaxf(lo, u);
    return __fmul_rn(1.41421356237f, erfinv_xla(u));
}

// FAST normal for the vecs path ONLY: values feed smooth math (no accept
// boundaries), so MUFU log + FFMA Horner is safe (~1e-5 output error).
__device__ __forceinline__ float jax_normal_fast(uint32_t bits) {
    const float lo = -0.99999994f;
    float f = u01(bits);                       // exact
    float u = __fadd_rn(__fmul_rn(f, 2.0f), lo);
    u = fmaxf(lo, u);
    float w = -__logf(fmaf(-u, u, 1.0f));      // ≈ -log(1-u²)
    float p;
    if (w < 5.0f) {
        w = w - 2.5f;
        p = 2.81022636e-08f;
        p = fmaf(p, w, 3.43273939e-07f);
        p = fmaf(p, w, -3.5233877e-06f);
        p = fmaf(p, w, -4.39150654e-06f);
        p = fmaf(p, w, 0.00021858087f);
        p = fmaf(p, w, -0.00125372503f);
        p = fmaf(p, w, -0.00417768164f);
        p = fmaf(p, w, 0.246640727f);
        p = fmaf(p, w, 1.50140941f);
    } else {
        w = sqrtf(w) - 3.0f;
        p = -0.000200214257f;
        p = fmaf(p, w, 0.000100950558f);
        p = fmaf(p, w, 0.00134934322f);
        p = fmaf(p, w, -0.00367342844f);
        p = fmaf(p, w, 0.00573950773f);
        p = fmaf(p, w, -0.0076224613f);
        p = fmaf(p, w, 0.00943887047f);
        p = fmaf(p, w, 1.00167406f);
        p = fmaf(p, w, 2.83297682f);
    }
    return 1.41421356237f * (p * u);
}

// jax _gamma_one(key, alpha=63.5, log_space=True) — exact chain
__device__ __forceinline__ float log_gamma_one(uint32_t gk0, uint32_t gk1) {
    const float one_third = 0.33333334f;
    float dg = __fsub_rn(63.5f, one_third);
    float cg = __fdiv_rn(one_third, sqrtf(dg));

    uint32_t key0, key1;
    tf2x32(gk0, gk1, 0u, 0u, key0, key1);

    while (true) {
        uint32_t nk0, nk1, xk0, xk1, Uk0, Uk1;
        tf2x32(key0, key1, 0u, 0u, nk0, nk1);
        tf2x32(key0, key1, 0u, 1u, xk0, xk1);
        tf2x32(key0, key1, 0u, 2u, Uk0, Uk1);
        key0 = nk0; key1 = nk1;

        float x, v;
        uint32_t cx0 = xk0, cx1 = xk1;
        while (true) {
            uint32_t s0, s1;
            tf2x32(cx0, cx1, 0u, 1u, s0, s1);
            x = jax_normal(rbits(s0, s1, 0u));
            v = __fadd_rn(1.0f, __fmul_rn(x, cg));
            if (v > 0.0f) break;
            uint32_t n0, n1;
            tf2x32(cx0, cx1, 0u, 0u, n0, n1);
            cx0 = n0; cx1 = n1;
        }

        float X = __fmul_rn(x, x);
        float V = __fmul_rn(__fmul_rn(v, v), v);
        float U = u01(rbits(Uk0, Uk1, 0u));

        float sq = __fsub_rn(1.0f, __fmul_rn(0.0331f, __fmul_rn(X, X)));
        bool cont;
        if (U < sq) {
            cont = false;
        } else {
            float th = __fadd_rn(__fmul_rn(X, 0.5f),
                                 __fmul_rn(dg, __fadd_rn(__fsub_rn(1.0f, V), logf(V))));
            cont = (logf(U) >= th);
        }
        if (!cont) return __fadd_rn(logf(V), logf(dg));
    }
}

// ================= mma.sync helpers =================
__device__ __forceinline__ uint32_t smem_u32(const void* p) {
    uint32_t a;
    asm("{ .reg .u64 t; cvta.to.shared.u64 t, %1; cvt.u32.u64 %0, t; }"
        : "=r"(a) : "l"(p));
    return a;
}
#define SWZ128(o) ((o) ^ (((o) >> 3) & 0x70))

#define LDM4(r, addr)                                                              \
    asm volatile("ldmatrix.sync.aligned.m8n8.x4.shared.b16 {%0,%1,%2,%3}, [%4];"   \
        : "=r"((r)[0]), "=r"((r)[1]), "=r"((r)[2]), "=r"((r)[3]) : "r"(addr))

#define MMA16816(c, a, b0, b1)                                                     \
    asm volatile("mma.sync.aligned.m16n8k16.row.col.f32.bf16.bf16.f32 "            \
        "{%0,%1,%2,%3}, {%4,%5,%6,%7}, {%8,%9}, {%0,%1,%2,%3};"                    \
        : "+f"((c)[0]), "+f"((c)[1]), "+f"((c)[2]), "+f"((c)[3])                   \
        : "r"((a)[0]), "r"((a)[1]), "r"((a)[2]), "r"((a)[3]), "r"(b0), "r"(b1))

#define CPASYNC16(dst, src)                                                        \
    asm volatile("cp.async.cg.shared.global [%0], [%1], 16;" :: "r"(dst), "l"(src))
#define CPCOMMIT()  asm volatile("cp.async.commit_group;" ::: "memory")
#define CPWAIT0()   asm volatile("cp.async.wait_group 0;" ::: "memory")

__device__ __forceinline__ uint32_t pack_bf2(float a, float b) {
    __nv_bfloat162 t = __floats2bfloat162_rn(a, b);
    return *reinterpret_cast<uint32_t*>(&t);
}

// smem layout (byte offsets from 1024-aligned base)
#define SM_BIAS   0
#define SM_NORM   512
#define SM_NPART  1024
#define SM_SA32(s) (2048 + (s) * 32768)      // f32 A stage, 32KB each
#define SM_AHL(s)  (67584 + (s) * 32768)     // [16KB Ahi | 16KB Alo]
#define SM_BHL(s)  (133120 + (s) * 32768)    // [16KB Bhi | 16KB Blo]
#define STG_STRIDE 132
#define SM_DYN    199680

// ---------------- Kernel 0: pre-convert + pre-swizzle W ----------------
__global__ __launch_bounds__(256) void convW_kernel(const float* __restrict__ W)
{
    int idx0 = (blockIdx.x * 256 + threadIdx.x) * 8;
#pragma unroll
    for (int q = 0; q < 8; q++) {
        int idx = idx0 + q;                 // 0..65535
        int row = idx >> 9;                 // 0..127
        int k = idx & 511;
        int kb = k >> 6;
        int k2 = k & 63;
        float w = W[idx];
        __nv_bfloat16 hi = __float2bfloat16_rn(w);
        float hif = __bfloat162float(hi);
        __nv_bfloat16 lo = __float2bfloat16_rn(__fsub_rn(w, hif));
        uint32_t off = kb * 32768u + SWZ128((uint32_t)(row * 128 + k2 * 2));
        *(__nv_bfloat16*)(g_bcvt + off) = hi;
        *(__nv_bfloat16*)(g_bcvt + off + 16384u) = lo;
    }
}

// ---------------- Kernel 1: pipelined split-bf16 mma GEMM + epilogue --------
__global__ __launch_bounds__(256) void gemm_mu_kernel(
    const float* __restrict__ A,
    const float* __restrict__ bias,
    float* __restrict__ out, float kld)
{
    extern __shared__ char dsm[];
    char* p = (char*)(((uintptr_t)dsm + 1023) & ~(uintptr_t)1023);
    uint32_t sb = smem_u32(p);

    int t = threadIdx.x;
    int wid = t >> 5;
    int lane = t & 31;
    int m0 = blockIdx.x * 128;

    int warp_m = wid & 3;
    int warp_n = wid >> 2;
    int m0w = warp_m * 32;
    int n0w = warp_n * 64;

    if (t < 128) *(float*)(p + SM_BIAS + t * 4) = bias[t];

    float c[2][8][4];
#pragma unroll
    for (int mt = 0; mt < 2; mt++)
#pragma unroll
        for (int nt = 0; nt < 8; nt++)
#pragma unroll
            for (int q = 0; q < 4; q++) c[mt][nt][q] = 0.0f;

    int a_row = (lane & 7) + ((lane >> 3) & 1) * 8;
    int a_kb  = (lane >> 4) * 16;
    int b_row = (lane & 7) + (lane >> 4) * 8;
    int b_kb  = ((lane >> 3) & 1) * 16;

    const float* Abase = A + (size_t)m0 * NHID;

    // prologue: issue chunk 0 (A f32 + B bf16 image)
    {
#pragma unroll
        for (int j = 0; j < 8; j++) {
            uint32_t u = (uint32_t)(t + j * 256);
            uint32_t row = u >> 4, kc = (u & 15) * 4;
            CPASYNC16(sb + SM_SA32(0) + u * 16, Abase + row * NHID + kc);
        }
        const unsigned char* srcB = g_bcvt;
#pragma unroll
        for (int j = 0; j < 8; j++) {
            uint32_t o = (uint32_t)(t + j * 256) * 16u;
            CPASYNC16(sb + SM_BHL(0) + o, srcB + o);
        }
        CPCOMMIT();
    }

    for (int kb = 0; kb < 8; kb++) {
        int buf = kb & 1;
        CPWAIT0();
        __syncthreads();

        if (kb < 7) {
            const float* srcA = Abase + (kb + 1) * 64;
#pragma unroll
            for (int j = 0; j < 8; j++) {
                uint32_t u = (uint32_t)(t + j * 256);
                uint32_t row = u >> 4, kc = (u & 15) * 4;
                CPASYNC16(sb + SM_SA32(buf ^ 1) + u * 16, srcA + row * NHID + kc);
            }
            const unsigned char* srcB = g_bcvt + (size_t)(kb + 1) * 32768u;
#pragma unroll
            for (int j = 0; j < 8; j++) {
                uint32_t o = (uint32_t)(t + j * 256) * 16u;
                CPASYNC16(sb + SM_BHL(buf ^ 1) + o, srcB + o);
            }
            CPCOMMIT();
        }

#pragma unroll
        for (int q = 0; q < 8; q++) {
            int fidx = q * 256 + t;
            int row = fidx >> 4;
            int kq = (fidx & 15) << 2;
            float4 a = *(const float4*)(p + SM_SA32(buf) + fidx * 16);
            uint32_t h01 = pack_bf2(a.x, a.y);
            uint32_t h23 = pack_bf2(a.z, a.w);
            float hx = __uint_as_float(h01 << 16);
            float hy = __uint_as_float(h01 & 0xFFFF0000u);
            float hz = __uint_as_float(h23 << 16);
            float hw = __uint_as_float(h23 & 0xFFFF0000u);
            uint32_t l01 = pack_bf2(__fsub_rn(a.x, hx), __fsub_rn(a.y, hy));
            uint32_t l23 = pack_bf2(__fsub_rn(a.z, hz), __fsub_rn(a.w, hw));
            uint32_t off = SWZ128((uint32_t)(row * 128 + kq * 2));
            *(uint2*)(p + SM_AHL(buf) + off) = make_uint2(h01, h23);
            *(uint2*)(p + SM_AHL(buf) + 16384 + off) = make_uint2(l01, l23);
        }
        __syncthreads();

#pragma unroll
        for (int ks = 0; ks < 4; ks++) {
            int kb2 = ks * 32;
            uint32_t ah[2][4], al[2][4];
#pragma unroll
            for (int mt = 0; mt < 2; mt++) {
                uint32_t off = SWZ128((uint32_t)(((m0w + mt * 16 + a_row) << 7) + kb2 + a_kb));
                LDM4(ah[mt], sb + SM_AHL(buf) + off);
                LDM4(al[mt], sb + SM_AHL(buf) + 16384 + off);
            }
#pragma unroll
            for (int half = 0; half < 2; half++) {
                uint32_t bh[2][4], bl[2][4];
#pragma unroll
                for (int g = 0; g < 2; g++) {
                    uint32_t off = SWZ128((uint32_t)(((n0w + half * 32 + g * 16 + b_row) << 7) + kb2 + b_kb));
                    LDM4(bh[g], sb + SM_BHL(buf) + off);
                    LDM4(bl[g], sb + SM_BHL(buf) + 16384 + off);
                }
#pragma unroll
                for (int mt = 0; mt < 2; mt++)
#pragma unroll
                    for (int n4 = 0; n4 < 4; n4++) {
                        int g = n4 >> 1, wch = (n4 & 1) * 2;
                        float* cc = c[mt][half * 4 + n4];
                        MMA16816(cc, ah[mt], bh[g][wch], bh[g][wch + 1]);
                        MMA16816(cc, ah[mt], bl[g][wch], bl[g][wch + 1]);
                        MMA16816(cc, al[mt], bh[g][wch], bh[g][wch + 1]);
                    }
            }
        }
    }
    __syncthreads();

    float* bias_s = (float*)(p + SM_BIAS);
    float* norm_s = (float*)(p + SM_NORM);
    float* npart  = (float*)(p + SM_NPART);
    float* stg    = (float*)(p + SM_SA32(0));

    float rs[4] = {0.0f, 0.0f, 0.0f, 0.0f};
#pragma unroll
    for (int nt = 0; nt < 8; nt++) {
        int col = n0w + nt * 8 + 2 * (lane & 3);
        float b0 = bias_s[col], b1 = bias_s[col + 1];
#pragma unroll
        for (int mt = 0; mt < 2; mt++) {
            c[mt][nt][0] += b0; c[mt][nt][1] += b1;
            c[mt][nt][2] += b0; c[mt][nt][3] += b1;
            rs[mt * 2 + 0] += c[mt][nt][0] * c[mt][nt][0] + c[mt][nt][1] * c[mt][nt][1];
            rs[mt * 2 + 1] += c[mt][nt][2] * c[mt][nt][2] + c[mt][nt][3] * c[mt][nt][3];
            int row = m0w + mt * 16 + (lane >> 2);
            *(float2*)(stg + row * STG_STRIDE + col) = make_float2(c[mt][nt][0], c[mt][nt][1]);
            *(float2*)(stg + (row + 8) * STG_STRIDE + col) = make_float2(c[mt][nt][2], c[mt][nt][3]);
        }
    }
#pragma unroll
    for (int i = 0; i < 4; i++) {
        rs[i] += __shfl_xor_sync(0xffffffffu, rs[i], 1);
        rs[i] += __shfl_xor_sync(0xffffffffu, rs[i], 2);
    }
    if ((lane & 3) == 0) {
        int rbase = m0w + (lane >> 2);
#pragma unroll
        for (int i = 0; i < 4; i++)
            npart[(rbase + i * 8) * 2 + warp_n] = rs[i];
    }
    __syncthreads();

    if (t < 128) {
        float nrm = sqrtf(npart[t * 2] + npart[t * 2 + 1]);
        norm_s[t] = nrm;
        int grow = m0 + t;
        float om = 1.0f - nrm;
        out[OFF_RED + grow] = om * om;
        out[OFF_KLD + grow] = kld;
    }
    __syncthreads();

    float4* muv = (float4*)(out + OFF_MU + (size_t)m0 * NLAT);
#pragma unroll
    for (int j = 0; j < 16; j++) {
        int idx = t * 16 + j;
        int r = idx >> 5;
        int c4 = idx & 31;
        float4 v = *(float4*)(stg + r * STG_STRIDE + c4 * 4);
        float nrm = norm_s[r];
        v.x /= nrm; v.y /= nrm; v.z /= nrm; v.w /= nrm;
        muv[r * 32 + c4] = v;
    }
}

// ---------------- Kernel 2: vMF weight rejection sampler (bit-exact) --------
__global__ __launch_bounds__(256) void wsample_kernel(Keys2 K, float A1, float A2,
                                                      float Xc, float Cc)
{
    int i = blockIdx.x * 256 + threadIdx.x;
    if (i >= NROWS) return;
    uint32_t ui = (uint32_t)i;
    float w = 0.0f;
#pragma unroll 1
    for (int t = 0; t < TMAX; t++) {
        uint32_t ga0, ga1, gb0, gb1;
        tf2x32(K.ka[t][0], K.ka[t][1], 0u, ui, ga0, ga1);
        tf2x32(K.kb[t][0], K.kb[t][1], 0u, ui, gb0, gb1);
        float lga = log_gamma_one(ga0, ga1);
        float lgb = log_gamma_one(gb0, gb1);
        float mx = fmaxf(lga, lgb);
        float gA = expf(__fsub_rn(lga, mx));
        float gB = expf(__fsub_rn(lgb, mx));
        float z = __fdiv_rn(gA, __fadd_rn(gA, gB));

        float wn = __fdiv_rn(__fsub_rn(1.0f, __fmul_rn(A1, z)),
                             __fsub_rn(1.0f, __fmul_rn(A2, z)));
        float u = u01(rbits(K.ku[t][0], K.ku[t][1], ui));
        float lhs = __fsub_rn(
            __fadd_rn(__fmul_rn(50.0f, wn),
                      __fmul_rn(127.0f, logf(__fsub_rn(1.0f, __fmul_rn(Xc, wn))))),
            Cc);
        if (lhs >= logf(u)) { w = wn; break; }
    }
    g_w[i] = w;
}

// ---------------- Kernel 3: fused normals (fast path) + orthogonalize -------
__global__ __launch_bounds__(256) void vecs_kernel(
    const float* __restrict__ mu, float* __restrict__ vecs,
    uint32_t kv0, uint32_t kv1, uint32_t kn0, uint32_t kn1)
{
    int wid = threadIdx.x >> 5;
    int lane = threadIdx.x & 31;
    int b = blockIdx.x * 2 + (wid >> 2);     // 4 warps share one b (mu L2 reuse)
    int n = wid & 3;
    int r = n * NB + b;                       // row index matches JAX layout
    const float* murow = mu + (size_t)b * NLAT;

    float4 m4 = __ldg((const float4*)(murow + lane * 4));

    uint32_t base = (uint32_t)r * 128u + (uint32_t)lane * 4u;
    float4 v4;
    v4.x = jax_normal_fast(rbits(kv0, kv1, base));
    v4.y = jax_normal_fast(rbits(kv0, kv1, base + 1u));
    v4.z = jax_normal_fast(rbits(kv0, kv1, base + 2u));
    v4.w = jax_normal_fast(rbits(kv0, kv1, base + 3u));

    float dot = m4.x * v4.x + m4.y * v4.y + m4.z * v4.z + m4.w * v4.w;
    float msq = m4.x * m4.x + m4.y * m4.y + m4.z * m4.z + m4.w * m4.w;
#pragma unroll
    for (int o = 16; o; o >>= 1) {
        dot += __shfl_xor_sync(0xffffffffu, dot, o);
        msq += __shfl_xor_sync(0xffffffffu, msq, o);
    }
    float tproj = dot * rsqrtf(msq);          // dot / ||mu||, smooth path

    float4 og;
    og.x = v4.x - m4.x * tproj;
    og.y = v4.y - m4.y * tproj;
    og.z = v4.z - m4.z * tproj;
    og.w = v4.w - m4.w * tproj;
    float osq = og.x * og.x + og.y * og.y + og.z * og.z + og.w * og.w;
#pragma unroll
    for (int o = 16; o; o >>= 1) osq += __shfl_xor_sync(0xffffffffu, osq, o);
    float rinv = rsqrtf(osq);                 // 1 / ||ortho||

    float w = 0.0f, nn = 0.0f;
    if (lane == 0) {
        w = g_w[r];
        nn = 1.0f + u01(rbits(kn0, kn1, (uint32_t)r));
    }
    w = __shfl_sync(0xffffffffu, w, 0);
    nn = __shfl_sync(0xffffffffu, nn, 0);
    float s = sqrtf(1.0f - w * w) * rinv;     // fold rinv into s

    float4 ov;
    ov.x = (og.x * s + m4.x * w) * nn;
    ov.y = (og.y * s + m4.y * w) * nn;
    ov.z = (og.z * s + m4.z * w) * nn;
    ov.w = (og.w * s + m4.w * w) * nn;
    *(float4*)(vecs + (size_t)r * NLAT + lane * 4) = ov;
}

// ---------------- Host ----------------
static double host_log_iv(double nu, double k) {
    const int M = 300;
    double logt[M];
    double mx = -1e300;
    for (int m = 0; m < M; m++) {
        double tv = (2.0 * m + nu) * log(k / 2.0) - lgamma(m + 1.0) - lgamma(m + nu + 1.0);
        logt[m] = tv;
        if (tv > mx) mx = tv;
    }
    double s = 0.0;
    for (int m = 0; m < M; m++) s += exp(logt[m] - mx);
    return mx + log(s);
}

extern "C" void kernel_launch(void* const* d_in, const int* in_sizes, int n_in,
                              void* d_out, int out_size)
{
    const float* lat = (const float*)d_in[0];
    const float* Wm  = (const float*)d_in[1];
    const float* bm  = (const float*)d_in[2];
    float* out = (float*)d_out;

    const double dd = 127.0, kap = 50.0;
    double b = dd / (sqrt(4.0 * kap * kap + dd * dd) + 2.0 * kap);
    double x = (1.0 - b) / (1.0 + b);
    double c = kap * x + dd * log(1.0 - x * x);
    float A1 = (float)(1.0 + b), A2 = (float)(1.0 - b);
    float Xc = (float)x, Cc = (float)c;

    const double D = 128.0;
    double liv0 = host_log_iv(D / 2.0, kap);
    double liv1 = host_log_iv(D / 2.0 + 1.0, kap);
    double ratio = exp(liv1 - liv0);
    double a_ = D / (2.0 * kap);
    double vmf = kap * (ratio + a_ - a_) + D * log(kap) / 2.0 - liv0
               - lgamma(D / 2.0 + 1.0) - D * log(2.0) / 2.0;
    float kld = (float)(vmf + log(2.0 / 1.0));

    uint32_t kw0, kw1, kv0, kv1, kn0, kn1;
    tf2x32(0u, 1u, 0u, 0u, kw0, kw1);
    tf2x32(0u, 1u, 0u, 1u, kv0, kv1);
    tf2x32(0u, 1u, 0u, 2u, kn0, kn1);

    Keys2 K;
    uint32_t c0 = kw0, c1 = kw1;
    for (int t = 0; t < TMAX; t++) {
        uint32_t nk0, nk1, kz0, kz1, ku0, ku1;
        tf2x32(c0, c1, 0u, 0u, nk0, nk1);
        tf2x32(c0, c1, 0u, 1u, kz0, kz1);
        tf2x32(c0, c1, 0u, 2u, ku0, ku1);
        tf2x32(kz0, kz1, 0u, 0u, K.ka[t][0], K.ka[t][1]);
        tf2x32(kz0, kz1, 0u, 1u, K.kb[t][0], K.kb[t][1]);
        K.ku[t][0] = ku0; K.ku[t][1] = ku1;
        c0 = nk0; c1 = nk1;
    }

    static cudaStream_t s1 = nullptr;
    static cudaEvent_t eFork = nullptr, eSide = nullptr;
    if (!s1) {
        cudaStreamCreateWithFlags(&s1, cudaStreamNonBlocking);
        cudaEventCreateWithFlags(&eFork, cudaEventDisableTiming);
        cudaEventCreateWithFlags(&eSide, cudaEventDisableTiming);
        cudaFuncSetAttribute(gemm_mu_kernel,
                             cudaFuncAttributeMaxDynamicSharedMemorySize, SM_DYN);
    }

    // fork: wsample on side stream (vecs needs g_w), GEMM path on main stream
    cudaEventRecord(eFork, 0);
    cudaStreamWaitEvent(s1, eFork, 0);
    wsample_kernel<<<NROWS / 256, 256, 0, s1>>>(K, A1, A2, Xc, Cc);
    cudaEventRecord(eSide, s1);

    convW_kernel<<<32, 256>>>(Wm);
    gemm_mu_kernel<<<NB / 128, 256, SM_DYN>>>(lat, bm, out, kld);

    cudaStreamWaitEvent(0, eSide, 0);
    vecs_kernel<<<NB / 2, 256>>>(out + OFF_MU, out + OFF_VECS, kv0, kv1, kn0, kn1);
}